// round 9
// baseline (speedup 1.0000x reference)
#include <cuda_runtime.h>
#include <cuda_fp16.h>

#define Nn    50000
#define Ee    800000
#define INDIM 128
#define EMB   32
#define ED    8
#define NL    4
#define NB    64
#define NOUT  10
#define EPS_BN 1e-5f
#define NBLK_SCAN 196   // ceil(Nn/256)

// ---------------- scratch (device globals) ----------------------------------
__device__ __align__(16) float  g_h[Nn * EMB];
__device__ __align__(16) float  g_p[Nn * EMB];
__device__ __align__(16) float  g_q[Nn * EMB];
__device__ __align__(16) float  g_y3[Nn * EMB];
__device__ __align__(16) float  g_y4[Nn * EMB];
__device__ __align__(16) __half g_yh[(size_t)Ee * EMB];   // y1/y2, fp16, original edge order
__device__ __align__(16) float  g_stats[NL * 4 * 2 * EMB];
__device__ __align__(16) float  g_pool[NB * EMB];
__device__ __align__(16) float  g_cnt[NB];
// CSR (built once per launch; dst is launch-invariant)
__device__ int g_deg[Nn];
__device__ int g_rowstart[Nn + 1];
__device__ int g_cursor[Nn];
__device__ int g_elist[Ee];
__device__ int g_bsum[NBLK_SCAN];
__device__ int g_boff[NBLK_SCAN];

#define STAT_IDX(l, stage, which, c) ((((l) * 4 + (stage)) * 2 + (which)) * EMB + (c))

// ---------------- helpers ---------------------------------------------------
__device__ __forceinline__ float4 f4add(float4 a, float4 b) {
    return make_float4(a.x + b.x, a.y + b.y, a.z + b.z, a.w + b.w);
}
__device__ __forceinline__ void f4fma(float4& a, float s, float4 w) {
    a.x = fmaf(s, w.x, a.x); a.y = fmaf(s, w.y, a.y);
    a.z = fmaf(s, w.z, a.z); a.w = fmaf(s, w.w, a.w);
}
__device__ __forceinline__ void store_h4(__half* p, float4 v) {
    union { __half2 h[2]; uint2 u; } cv;
    cv.h[0] = __float22half2_rn(make_float2(v.x, v.y));
    cv.h[1] = __float22half2_rn(make_float2(v.z, v.w));
    *(uint2*)p = cv.u;
}
__device__ __forceinline__ float4 load_h4(const __half* p) {
    union { uint2 u; __half2 h[2]; } cv;
    cv.u = *(const uint2*)p;
    float2 a = __half22float2(cv.h[0]);
    float2 b = __half22float2(cv.h[1]);
    return make_float4(a.x, a.y, b.x, b.y);
}

__device__ __forceinline__ void stats_warp_to_shared(float4 sum, float4 ss, int lane,
                                                     int c0, float* s_sum, float* s_ss) {
#pragma unroll
    for (int off = 8; off < 32; off <<= 1) {
        sum.x += __shfl_xor_sync(0xffffffffu, sum.x, off);
        sum.y += __shfl_xor_sync(0xffffffffu, sum.y, off);
        sum.z += __shfl_xor_sync(0xffffffffu, sum.z, off);
        sum.w += __shfl_xor_sync(0xffffffffu, sum.w, off);
        ss.x  += __shfl_xor_sync(0xffffffffu, ss.x, off);
        ss.y  += __shfl_xor_sync(0xffffffffu, ss.y, off);
        ss.z  += __shfl_xor_sync(0xffffffffu, ss.z, off);
        ss.w  += __shfl_xor_sync(0xffffffffu, ss.w, off);
    }
    if (lane < 8) {
        atomicAdd(&s_sum[c0 + 0], sum.x); atomicAdd(&s_sum[c0 + 1], sum.y);
        atomicAdd(&s_sum[c0 + 2], sum.z); atomicAdd(&s_sum[c0 + 3], sum.w);
        atomicAdd(&s_ss[c0 + 0], ss.x);   atomicAdd(&s_ss[c0 + 1], ss.y);
        atomicAdd(&s_ss[c0 + 2], ss.z);   atomicAdd(&s_ss[c0 + 3], ss.w);
    }
}

__device__ __forceinline__ void bn_coeffs(int l, int stage, float inv_n,
                                          const float* __restrict__ gamma,
                                          const float* __restrict__ beta,
                                          int c0, float sc[4], float sh[4]) {
#pragma unroll
    for (int i = 0; i < 4; i++) {
        int c = c0 + i;
        float s1 = g_stats[STAT_IDX(l, stage, 0, c)];
        float s2 = g_stats[STAT_IDX(l, stage, 1, c)];
        float mu = s1 * inv_n;
        float var = s2 * inv_n - mu * mu;
        float rs = rsqrtf(var + EPS_BN);
        sc[i] = rs * gamma[c];
        sh[i] = beta[c] - mu * sc[i];
    }
}

// ---------------- init + CSR build ------------------------------------------
__global__ void k_zero_once() {
    int i = blockIdx.x * blockDim.x + threadIdx.x;
    if (i < NL * 4 * 2 * EMB) g_stats[i] = 0.f;
    if (i < NB * EMB) g_pool[i] = 0.f;
    if (i < NB) g_cnt[i] = 0.f;
    if (i < Nn) g_deg[i] = 0;
}
__global__ void k_hist(const int* __restrict__ ei) {
    int i = blockIdx.x * blockDim.x + threadIdx.x;
    if (i < Ee) atomicAdd(&g_deg[ei[Ee + i]], 1);
}
__global__ void k_scan1() {
    __shared__ int s[256];
    int t = threadIdx.x;
    int i = blockIdx.x * 256 + t;
    int v = (i < Nn) ? g_deg[i] : 0;
    s[t] = v;
    __syncthreads();
#pragma unroll
    for (int off = 1; off < 256; off <<= 1) {
        int add = (t >= off) ? s[t - off] : 0;
        __syncthreads();
        s[t] += add;
        __syncthreads();
    }
    if (i < Nn) g_rowstart[i + 1] = s[t];
    if (t == 255) g_bsum[blockIdx.x] = s[255];
}
__global__ void k_scan2() {
    __shared__ int s[256];
    int t = threadIdx.x;
    int v = (t < NBLK_SCAN) ? g_bsum[t] : 0;
    s[t] = v;
    __syncthreads();
#pragma unroll
    for (int off = 1; off < 256; off <<= 1) {
        int add = (t >= off) ? s[t - off] : 0;
        __syncthreads();
        s[t] += add;
        __syncthreads();
    }
    if (t < NBLK_SCAN) g_boff[t] = s[t] - v;   // exclusive
}
__global__ void k_scan3() {
    int i = blockIdx.x * blockDim.x + threadIdx.x;
    if (i < Nn) {
        int v = g_rowstart[i + 1] + g_boff[i >> 8];
        g_rowstart[i + 1] = v;
        g_cursor[i] = v - g_deg[i];
    }
    if (i == 0) g_rowstart[0] = 0;
}
__global__ void k_fill(const int* __restrict__ ei) {
    int i = blockIdx.x * blockDim.x + threadIdx.x;
    if (i < Ee) {
        int d = ei[Ee + i];
        int pos = atomicAdd(&g_cursor[d], 1);
        g_elist[pos] = i;
    }
}

// ---------------- lin_in: h = x @ W + b -------------------------------------
__global__ void k_lin_in(const float* __restrict__ x, const float* __restrict__ w,
                         const float* __restrict__ b) {
    __shared__ float ws[INDIM * EMB];
    __shared__ float xs[8][INDIM];
    int tx = threadIdx.x, ty = threadIdx.y;
    int tid = ty * 32 + tx;
    for (int i = tid; i < INDIM * EMB; i += 256) ws[i] = w[i];
    int base = blockIdx.x * 8;
    for (int i = tid; i < 8 * INDIM; i += 256) {
        int nloc = i >> 7, k = i & 127;
        xs[nloc][k] = x[(base + nloc) * INDIM + k];
    }
    __syncthreads();
    float acc = b[tx];
#pragma unroll 8
    for (int k = 0; k < INDIM; k++) acc = fmaf(xs[ty][k], ws[k * EMB + tx], acc);
    g_h[(base + ty) * EMB + tx] = acc;
}

// ---------------- pq (layer 0): p,q from g_h --------------------------------
__global__ void k_pq(const float* __restrict__ w1, const float* __restrict__ b1) {
    __shared__ float wd[EMB * EMB];
    __shared__ float wsr[EMB * EMB];
    __shared__ float hs[8][EMB];
    int tx = threadIdx.x, ty = threadIdx.y;
    int tid = ty * 32 + tx;
    for (int i = tid; i < EMB * EMB; i += 256) { wd[i] = w1[i]; wsr[i] = w1[EMB * EMB + i]; }
    int base = blockIdx.x * 8;
    hs[ty][tx] = g_h[(base + ty) * EMB + tx];
    __syncthreads();
    float ap = b1[tx], aq = 0.f;
#pragma unroll
    for (int k = 0; k < EMB; k++) {
        float hv = hs[ty][k];
        ap = fmaf(hv, wd[k * EMB + tx], ap);
        aq = fmaf(hv, wsr[k * EMB + tx], aq);
    }
    g_p[(base + ty) * EMB + tx] = ap;
    g_q[(base + ty) * EMB + tx] = aq;
}

// ---- fused u3(prev layer) + pq(this layer) ---------------------------------
__global__ void k_u3pq(const float* __restrict__ w1, const float* __restrict__ b1,
                       const float* __restrict__ g2, const float* __restrict__ be2,
                       int prev) {
    __shared__ float wd[EMB * EMB];
    __shared__ float wsr[EMB * EMB];
    __shared__ float hs[8][EMB];
    int tx = threadIdx.x, ty = threadIdx.y;
    int tid = ty * 32 + tx;
    for (int i = tid; i < EMB * EMB; i += 256) { wd[i] = w1[i]; wsr[i] = w1[EMB * EMB + i]; }
    float s1 = g_stats[STAT_IDX(prev, 3, 0, tx)];
    float s2 = g_stats[STAT_IDX(prev, 3, 1, tx)];
    float mu = s1 * (1.f / Nn);
    float var = s2 * (1.f / Nn) - mu * mu;
    float rs = rsqrtf(var + EPS_BN);
    float sc = rs * g2[tx];
    float sh = be2[tx] - mu * sc;
    int base = blockIdx.x * 8;
    int n = base + ty;
    float hv = g_h[n * EMB + tx] + fmaxf(fmaf(g_y4[n * EMB + tx], sc, sh), 0.f);
    g_h[n * EMB + tx] = hv;
    hs[ty][tx] = hv;
    __syncthreads();
    float ap = b1[tx], aq = 0.f;
#pragma unroll
    for (int k = 0; k < EMB; k++) {
        float h2 = hs[ty][k];
        ap = fmaf(h2, wd[k * EMB + tx], ap);
        aq = fmaf(h2, wsr[k * EMB + tx], aq);
    }
    g_p[n * EMB + tx] = ap;
    g_q[n * EMB + tx] = aq;
}

// ---- E1: y1 = p[dst]+q[src]+ea@Wc -> g_yh (original order); stats stage 0 --
// Wc in shared (low regs, high occ); (src,dst) software-pipelined.
__global__ void __launch_bounds__(256) k_e1(const int* __restrict__ ei,
                     const float* __restrict__ ea,
                     const float* __restrict__ wc, int layer) {
    __shared__ float4 s_w[64];      // [k][cg]
    __shared__ float s_sum[EMB], s_ss[EMB];
    int tid = threadIdx.x;
    if (tid < 64) s_w[tid] = *(const float4*)(wc + (tid >> 3) * EMB + (tid & 7) * 4);
    if (tid < EMB) { s_sum[tid] = 0.f; s_ss[tid] = 0.f; }
    __syncthreads();
    int lane = tid & 31;
    int es = lane >> 3, cg = lane & 7, c0 = cg * 4;
    int nw = gridDim.x * (blockDim.x >> 5);
    int qd = blockIdx.x * (blockDim.x >> 5) + (tid >> 5);
    float4 sum = make_float4(0, 0, 0, 0), ss = make_float4(0, 0, 0, 0);
    const int NQ = Ee / 4;
    int s_nxt = 0, d_nxt = 0;
    if (qd < NQ) {
        int e = qd * 4 + es;
        s_nxt = ei[e];
        d_nxt = ei[Ee + e];
    }
    while (qd < NQ) {
        int e = qd * 4 + es;
        int s = s_nxt, d = d_nxt;
        int qn = qd + nw;
        if (qn < NQ) {                 // prefetch next indices (overlaps gather latency)
            int e2 = qn * 4 + es;
            s_nxt = ei[e2];
            d_nxt = ei[Ee + e2];
        }
        float4 pv = *(const float4*)(g_p + d * EMB + c0);
        float4 qv = *(const float4*)(g_q + s * EMB + c0);
        const float4* eap = (const float4*)(ea + (size_t)e * ED);
        float4 e0 = eap[0], e1v = eap[1];
        float4 y = f4add(pv, qv);
        f4fma(y, e0.x, s_w[0 * 8 + cg]); f4fma(y, e0.y, s_w[1 * 8 + cg]);
        f4fma(y, e0.z, s_w[2 * 8 + cg]); f4fma(y, e0.w, s_w[3 * 8 + cg]);
        f4fma(y, e1v.x, s_w[4 * 8 + cg]); f4fma(y, e1v.y, s_w[5 * 8 + cg]);
        f4fma(y, e1v.z, s_w[6 * 8 + cg]); f4fma(y, e1v.w, s_w[7 * 8 + cg]);
        store_h4(g_yh + (size_t)e * EMB + c0, y);
        sum = f4add(sum, y);
        ss.x = fmaf(y.x, y.x, ss.x); ss.y = fmaf(y.y, y.y, ss.y);
        ss.z = fmaf(y.z, y.z, ss.z); ss.w = fmaf(y.w, y.w, ss.w);
        qd = qn;
    }
    stats_warp_to_shared(sum, ss, lane, c0, s_sum, s_ss);
    __syncthreads();
    if (tid < EMB) {
        atomicAdd(&g_stats[STAT_IDX(layer, 0, 0, tid)], s_sum[tid]);
        atomicAdd(&g_stats[STAT_IDX(layer, 0, 1, tid)], s_ss[tid]);
    }
}

// ---- E2 (streaming): m1 = relu(bn(y1)); y2 = m1@W2+b2 in place; stats 1 ----
__global__ void __launch_bounds__(256) k_e2(const float* __restrict__ w2,
                     const float* __restrict__ b2,
                     const float* __restrict__ g1, const float* __restrict__ be1, int layer) {
    __shared__ float s_w2[EMB * EMB];
    __shared__ float s_sum[EMB], s_ss[EMB];
    int tid = threadIdx.x;
    for (int i = tid; i < EMB * EMB; i += 256) s_w2[i] = w2[i];
    if (tid < EMB) { s_sum[tid] = 0.f; s_ss[tid] = 0.f; }
    __syncthreads();
    int lane = tid & 31;
    int es = lane >> 3, cg = lane & 7, c0 = cg * 4, base = lane & 24;
    float sc[4], sh[4];
    bn_coeffs(layer, 0, 1.f / Ee, g1, be1, c0, sc, sh);
    float4 bb = *(const float4*)(b2 + c0);
    const float4* w2v = (const float4*)s_w2;
    int nw = gridDim.x * (blockDim.x >> 5);
    int gw = blockIdx.x * (blockDim.x >> 5) + (tid >> 5);
    float4 sum = make_float4(0, 0, 0, 0), ssq = make_float4(0, 0, 0, 0);
    for (int qd = gw; qd < Ee / 4; qd += nw) {
        int e = qd * 4 + es;
        float4 y1 = load_h4(g_yh + (size_t)e * EMB + c0);
        float m[4];
        m[0] = fmaxf(fmaf(y1.x, sc[0], sh[0]), 0.f);
        m[1] = fmaxf(fmaf(y1.y, sc[1], sh[1]), 0.f);
        m[2] = fmaxf(fmaf(y1.z, sc[2], sh[2]), 0.f);
        m[3] = fmaxf(fmaf(y1.w, sc[3], sh[3]), 0.f);
        float4 acc = bb;
#pragma unroll
        for (int j = 0; j < EMB; j++) {
            float mj = __shfl_sync(0xffffffffu, m[j & 3], base + (j >> 2));
            f4fma(acc, mj, w2v[j * 8 + cg]);
        }
        store_h4(g_yh + (size_t)e * EMB + c0, acc);
        sum = f4add(sum, acc);
        ssq.x = fmaf(acc.x, acc.x, ssq.x); ssq.y = fmaf(acc.y, acc.y, ssq.y);
        ssq.z = fmaf(acc.z, acc.z, ssq.z); ssq.w = fmaf(acc.w, acc.w, ssq.w);
    }
    stats_warp_to_shared(sum, ssq, lane, c0, s_sum, s_ss);
    __syncthreads();
    if (tid < EMB) {
        atomicAdd(&g_stats[STAT_IDX(layer, 1, 0, tid)], s_sum[tid]);
        atomicAdd(&g_stats[STAT_IDX(layer, 1, 1, tid)], s_ss[tid]);
    }
}

// ---- fused E3+U1: aggr via elist gathers (prefetched); y3; stats stage 2 ---
__global__ void __launch_bounds__(256) k_e3u1(const float* __restrict__ w,
                       const float* __restrict__ b,
                       const float* __restrict__ g2, const float* __restrict__ be2,
                       int layer) {
    __shared__ float sw[2 * EMB * EMB];
    __shared__ float s_sum[EMB], s_ss[EMB];
    int tid = threadIdx.x;
    for (int i = tid; i < 2 * EMB * EMB; i += 256) sw[i] = w[i];
    if (tid < EMB) { s_sum[tid] = 0.f; s_ss[tid] = 0.f; }
    __syncthreads();
    int lane = tid & 31;
    int es = lane >> 3, cg = lane & 7, c0 = cg * 4, base = lane & 24;
    float4 sum = make_float4(0, 0, 0, 0), ssq = make_float4(0, 0, 0, 0);

    int quad = blockIdx.x * 8 + (tid >> 5);
    if (quad * 4 < Nn) {
        float sc[4], sh[4];
        bn_coeffs(layer, 1, 1.f / Ee, g2, be2, c0, sc, sh);
        int n = quad * 4 + es;
        int rs = g_rowstart[n], re = g_rowstart[n + 1];
        float4 ag = make_float4(0, 0, 0, 0);
        int e_nxt = (rs < re) ? g_elist[rs] : 0;
        for (int i = rs; i < re; i++) {
            int e = e_nxt;
            if (i + 1 < re) e_nxt = g_elist[i + 1];   // prefetch next index
            float4 y = load_h4(g_yh + (size_t)e * EMB + c0);
            ag.x += fmaxf(fmaf(y.x, sc[0], sh[0]), 0.f);
            ag.y += fmaxf(fmaf(y.y, sc[1], sh[1]), 0.f);
            ag.z += fmaxf(fmaf(y.z, sc[2], sh[2]), 0.f);
            ag.w += fmaxf(fmaf(y.w, sc[3], sh[3]), 0.f);
        }
        float4 h4 = *(const float4*)(g_h + n * EMB + c0);
        float hr[4] = {h4.x, h4.y, h4.z, h4.w};
        float ar[4] = {ag.x, ag.y, ag.z, ag.w};
        const float4* swv = (const float4*)sw;
        float4 acc = *(const float4*)(b + c0);
#pragma unroll
        for (int j = 0; j < EMB; j++) {
            float hj = __shfl_sync(0xffffffffu, hr[j & 3], base + (j >> 2));
            f4fma(acc, hj, swv[j * 8 + cg]);
        }
#pragma unroll
        for (int j = 0; j < EMB; j++) {
            float aj = __shfl_sync(0xffffffffu, ar[j & 3], base + (j >> 2));
            f4fma(acc, aj, swv[(EMB + j) * 8 + cg]);
        }
        *(float4*)(g_y3 + n * EMB + c0) = acc;
        sum = acc;
        ssq.x = acc.x * acc.x; ssq.y = acc.y * acc.y;
        ssq.z = acc.z * acc.z; ssq.w = acc.w * acc.w;
    }
    stats_warp_to_shared(sum, ssq, lane, c0, s_sum, s_ss);
    __syncthreads();
    if (tid < EMB) {
        atomicAdd(&g_stats[STAT_IDX(layer, 2, 0, tid)], s_sum[tid]);
        atomicAdd(&g_stats[STAT_IDX(layer, 2, 1, tid)], s_ss[tid]);
    }
}

// ---------------- U2: r = relu(bn(y3)) ; y4 = r@Wu2+b ; stats stage 3 -------
__global__ void k_u2(const float* __restrict__ w2, const float* __restrict__ b2,
                     const float* __restrict__ g1, const float* __restrict__ be1, int layer) {
    __shared__ float s_w2[EMB * EMB];
    __shared__ float s_sum[EMB], s_ss[EMB];
    int tid = threadIdx.x;
    for (int i = tid; i < EMB * EMB; i += 256) s_w2[i] = w2[i];
    if (tid < EMB) { s_sum[tid] = 0.f; s_ss[tid] = 0.f; }
    __syncthreads();
    int lane = tid & 31;
    int es = lane >> 3, cg = lane & 7, c0 = cg * 4, base = lane & 24;
    float sc[4], sh[4];
    bn_coeffs(layer, 2, 1.f / Nn, g1, be1, c0, sc, sh);
    float4 bb = *(const float4*)(b2 + c0);
    const float4* w2v = (const float4*)s_w2;
    int nw = gridDim.x * (blockDim.x >> 5);
    int gw = blockIdx.x * (blockDim.x >> 5) + (tid >> 5);
    float4 sum = make_float4(0, 0, 0, 0), ssq = make_float4(0, 0, 0, 0);
    for (int qd = gw; qd < Nn / 4; qd += nw) {
        int n = qd * 4 + es;
        float4 y1 = *(const float4*)(g_y3 + n * EMB + c0);
        float m[4];
        m[0] = fmaxf(fmaf(y1.x, sc[0], sh[0]), 0.f);
        m[1] = fmaxf(fmaf(y1.y, sc[1], sh[1]), 0.f);
        m[2] = fmaxf(fmaf(y1.z, sc[2], sh[2]), 0.f);
        m[3] = fmaxf(fmaf(y1.w, sc[3], sh[3]), 0.f);
        float4 acc = bb;
#pragma unroll
        for (int j = 0; j < EMB; j++) {
            float mj = __shfl_sync(0xffffffffu, m[j & 3], base + (j >> 2));
            f4fma(acc, mj, w2v[j * 8 + cg]);
        }
        *(float4*)(g_y4 + n * EMB + c0) = acc;
        sum = f4add(sum, acc);
        ssq.x = fmaf(acc.x, acc.x, ssq.x); ssq.y = fmaf(acc.y, acc.y, ssq.y);
        ssq.z = fmaf(acc.z, acc.z, ssq.z); ssq.w = fmaf(acc.w, acc.w, ssq.w);
    }
    stats_warp_to_shared(sum, ssq, lane, c0, s_sum, s_ss);
    __syncthreads();
    if (tid < EMB) {
        atomicAdd(&g_stats[STAT_IDX(layer, 3, 0, tid)], s_sum[tid]);
        atomicAdd(&g_stats[STAT_IDX(layer, 3, 1, tid)], s_ss[tid]);
    }
}

// ---- final layer: h_final = h + relu(bn(y4)); pool atomics -----------------
__global__ void k_u3pool(const int* __restrict__ batch,
                         const float* __restrict__ g2, const float* __restrict__ be2,
                         int layer) {
    int idx = blockIdx.x * blockDim.x + threadIdx.x;
    if (idx >= Nn * 8) return;
    int n = idx >> 3, cg = idx & 7, c0 = cg * 4;
    float sc[4], sh[4];
    bn_coeffs(layer, 3, 1.f / Nn, g2, be2, c0, sc, sh);
    float4 y = *(const float4*)(g_y4 + n * EMB + c0);
    float4 h = *(const float4*)(g_h + n * EMB + c0);
    h.x += fmaxf(fmaf(y.x, sc[0], sh[0]), 0.f);
    h.y += fmaxf(fmaf(y.y, sc[1], sh[1]), 0.f);
    h.z += fmaxf(fmaf(y.z, sc[2], sh[2]), 0.f);
    h.w += fmaxf(fmaf(y.w, sc[3], sh[3]), 0.f);
    int b = batch[n];
    float* pp = g_pool + b * EMB + c0;
    atomicAdd(pp + 0, h.x); atomicAdd(pp + 1, h.y);
    atomicAdd(pp + 2, h.z); atomicAdd(pp + 3, h.w);
    if (cg == 0) atomicAdd(&g_cnt[b], 1.0f);
}

__global__ void k_pred(const float* __restrict__ pw, const float* __restrict__ pb,
                       float* __restrict__ out) {
    int t = threadIdx.x;
    if (t >= NB * NOUT) return;
    int b = t / NOUT, o = t % NOUT;
    float inv = 1.f / fmaxf(g_cnt[b], 1.f);
    float s = 0.f;
#pragma unroll
    for (int j = 0; j < EMB; j++) s = fmaf(g_pool[b * EMB + j], pw[j * NOUT + o], s);
    out[t] = pb[o] + s * inv;
}

// ---------------- launch -----------------------------------------------------
extern "C" void kernel_launch(void* const* d_in, const int* in_sizes, int n_in,
                              void* d_out, int out_size) {
    const float *x, *edge_attr, *lin_in_w, *lin_in_b;
    const float *msg_w1, *msg_b1, *msg_g1, *msg_be1, *msg_w2, *msg_b2, *msg_g2, *msg_be2;
    const float *upd_w1, *upd_b1, *upd_g1, *upd_be1, *upd_w2, *upd_b2, *upd_g2, *upd_be2;
    const float *pred_w, *pred_b;
    const int *edge_idx, *batch;

    if (in_sizes[1] == 2 * Ee) {
        x        = (const float*)d_in[0];
        edge_idx = (const int*)  d_in[1];
        edge_attr= (const float*)d_in[2];
        batch    = (const int*)  d_in[3];
        lin_in_w = (const float*)d_in[4];
        lin_in_b = (const float*)d_in[5];
        msg_w1   = (const float*)d_in[6];
        msg_b1   = (const float*)d_in[7];
        msg_g1   = (const float*)d_in[8];
        msg_be1  = (const float*)d_in[9];
        msg_w2   = (const float*)d_in[10];
        msg_b2   = (const float*)d_in[11];
        msg_g2   = (const float*)d_in[12];
        msg_be2  = (const float*)d_in[13];
        upd_w1   = (const float*)d_in[14];
        upd_b1   = (const float*)d_in[15];
        upd_g1   = (const float*)d_in[16];
        upd_be1  = (const float*)d_in[17];
        upd_w2   = (const float*)d_in[18];
        upd_b2   = (const float*)d_in[19];
        upd_g2   = (const float*)d_in[20];
        upd_be2  = (const float*)d_in[21];
        pred_w   = (const float*)d_in[22];
        pred_b   = (const float*)d_in[23];
    } else {
        x        = (const float*)d_in[0];
        edge_attr= (const float*)d_in[1];
        lin_in_w = (const float*)d_in[2];
        lin_in_b = (const float*)d_in[3];
        msg_w1   = (const float*)d_in[4];
        msg_b1   = (const float*)d_in[5];
        msg_g1   = (const float*)d_in[6];
        msg_be1  = (const float*)d_in[7];
        msg_w2   = (const float*)d_in[8];
        msg_b2   = (const float*)d_in[9];
        msg_g2   = (const float*)d_in[10];
        msg_be2  = (const float*)d_in[11];
        upd_w1   = (const float*)d_in[12];
        upd_b1   = (const float*)d_in[13];
        upd_g1   = (const float*)d_in[14];
        upd_be1  = (const float*)d_in[15];
        upd_w2   = (const float*)d_in[16];
        upd_b2   = (const float*)d_in[17];
        upd_g2   = (const float*)d_in[18];
        upd_be2  = (const float*)d_in[19];
        pred_w   = (const float*)d_in[20];
        pred_b   = (const float*)d_in[21];
        edge_idx = (const int*)  d_in[22];
        batch    = (const int*)  d_in[23];
    }
    float* out = (float*)d_out;

    // init + CSR build (launch-invariant graph structure)
    k_zero_once<<<NBLK_SCAN, 256>>>();
    k_hist<<<(Ee + 255) / 256, 256>>>(edge_idx);
    k_scan1<<<NBLK_SCAN, 256>>>();
    k_scan2<<<1, 256>>>();
    k_scan3<<<NBLK_SCAN, 256>>>();
    k_fill<<<(Ee + 255) / 256, 256>>>(edge_idx);

    k_lin_in<<<Nn / 8, dim3(32, 8)>>>(x, lin_in_w, lin_in_b);
    for (int l = 0; l < NL; l++) {
        const float* w1 = msg_w1 + l * (2 * EMB + ED) * EMB;
        if (l == 0)
            k_pq<<<Nn / 8, dim3(32, 8)>>>(w1, msg_b1);
        else
            k_u3pq<<<Nn / 8, dim3(32, 8)>>>(w1, msg_b1 + l * EMB,
                                            upd_g2 + (l - 1) * EMB, upd_be2 + (l - 1) * EMB,
                                            l - 1);
        k_e1<<<1184, 256>>>(edge_idx, edge_attr, w1 + 2 * EMB * EMB, l);
        k_e2<<<1184, 256>>>(msg_w2 + l * EMB * EMB, msg_b2 + l * EMB,
                            msg_g1 + l * EMB, msg_be1 + l * EMB, l);
        k_e3u1<<<(Nn / 4 + 7) / 8, 256>>>(upd_w1 + l * 2 * EMB * EMB, upd_b1 + l * EMB,
                                          msg_g2 + l * EMB, msg_be2 + l * EMB, l);
        k_u2<<<1184, 256>>>(upd_w2 + l * EMB * EMB, upd_b2 + l * EMB,
                            upd_g1 + l * EMB, upd_be1 + l * EMB, l);
    }
    k_u3pool<<<(Nn * 8 + 255) / 256, 256>>>(batch, upd_g2 + (NL - 1) * EMB,
                                            upd_be2 + (NL - 1) * EMB, NL - 1);
    k_pred<<<1, NB * NOUT>>>(pred_w, pred_b, out);
}

// round 10
// speedup vs baseline: 1.0095x; 1.0095x over previous
#include <cuda_runtime.h>
#include <cuda_fp16.h>

#define Nn    50000
#define Ee    800000
#define INDIM 128
#define EMB   32
#define ED    8
#define NL    4
#define NB    64
#define NOUT  10
#define EPS_BN 1e-5f
#define NBLK_SCAN 196   // ceil(Nn/256)
#define NSM   148

// ---------------- scratch (device globals) ----------------------------------
__device__ __align__(16) float  g_h[Nn * EMB];
__device__ __align__(16) float  g_p[Nn * EMB];
__device__ __align__(16) float  g_q[Nn * EMB];
__device__ __align__(16) float  g_y3[Nn * EMB];
__device__ __align__(16) float  g_y4[Nn * EMB];
__device__ __align__(16) __half g_yh[(size_t)Ee * EMB];   // y1/y2, fp16, original edge order
__device__ __align__(16) float  g_stats[NL * 4 * 2 * EMB];
__device__ __align__(16) float  g_pool[NB * EMB];
__device__ __align__(16) float  g_cnt[NB];
// CSR (built once per launch; dst is launch-invariant)
__device__ int g_deg[Nn];
__device__ int g_rowstart[Nn + 1];
__device__ int g_cursor[Nn];
__device__ int g_elist[Ee];
__device__ int g_bsum[NBLK_SCAN];
__device__ int g_boff[NBLK_SCAN];

#define STAT_IDX(l, stage, which, c) ((((l) * 4 + (stage)) * 2 + (which)) * EMB + (c))

// ---------------- helpers ---------------------------------------------------
__device__ __forceinline__ float4 f4add(float4 a, float4 b) {
    return make_float4(a.x + b.x, a.y + b.y, a.z + b.z, a.w + b.w);
}
__device__ __forceinline__ void f4fma(float4& a, float s, float4 w) {
    a.x = fmaf(s, w.x, a.x); a.y = fmaf(s, w.y, a.y);
    a.z = fmaf(s, w.z, a.z); a.w = fmaf(s, w.w, a.w);
}
__device__ __forceinline__ void store_h4(__half* p, float4 v) {
    union { __half2 h[2]; uint2 u; } cv;
    cv.h[0] = __float22half2_rn(make_float2(v.x, v.y));
    cv.h[1] = __float22half2_rn(make_float2(v.z, v.w));
    *(uint2*)p = cv.u;
}
__device__ __forceinline__ float4 load_h4(const __half* p) {
    union { uint2 u; __half2 h[2]; } cv;
    cv.u = *(const uint2*)p;
    float2 a = __half22float2(cv.h[0]);
    float2 b = __half22float2(cv.h[1]);
    return make_float4(a.x, a.y, b.x, b.y);
}

__device__ __forceinline__ void stats_warp_to_shared(float4 sum, float4 ss, int lane,
                                                     int c0, float* s_sum, float* s_ss) {
#pragma unroll
    for (int off = 8; off < 32; off <<= 1) {
        sum.x += __shfl_xor_sync(0xffffffffu, sum.x, off);
        sum.y += __shfl_xor_sync(0xffffffffu, sum.y, off);
        sum.z += __shfl_xor_sync(0xffffffffu, sum.z, off);
        sum.w += __shfl_xor_sync(0xffffffffu, sum.w, off);
        ss.x  += __shfl_xor_sync(0xffffffffu, ss.x, off);
        ss.y  += __shfl_xor_sync(0xffffffffu, ss.y, off);
        ss.z  += __shfl_xor_sync(0xffffffffu, ss.z, off);
        ss.w  += __shfl_xor_sync(0xffffffffu, ss.w, off);
    }
    if (lane < 8) {
        atomicAdd(&s_sum[c0 + 0], sum.x); atomicAdd(&s_sum[c0 + 1], sum.y);
        atomicAdd(&s_sum[c0 + 2], sum.z); atomicAdd(&s_sum[c0 + 3], sum.w);
        atomicAdd(&s_ss[c0 + 0], ss.x);   atomicAdd(&s_ss[c0 + 1], ss.y);
        atomicAdd(&s_ss[c0 + 2], ss.z);   atomicAdd(&s_ss[c0 + 3], ss.w);
    }
}

__device__ __forceinline__ void bn_coeffs(int l, int stage, float inv_n,
                                          const float* __restrict__ gamma,
                                          const float* __restrict__ beta,
                                          int c0, float sc[4], float sh[4]) {
#pragma unroll
    for (int i = 0; i < 4; i++) {
        int c = c0 + i;
        float s1 = g_stats[STAT_IDX(l, stage, 0, c)];
        float s2 = g_stats[STAT_IDX(l, stage, 1, c)];
        float mu = s1 * inv_n;
        float var = s2 * inv_n - mu * mu;
        float rs = rsqrtf(var + EPS_BN);
        sc[i] = rs * gamma[c];
        sh[i] = beta[c] - mu * sc[i];
    }
}

// ---------------- init + CSR build ------------------------------------------
__global__ void k_zero_once() {
    int i = blockIdx.x * blockDim.x + threadIdx.x;
    if (i < NL * 4 * 2 * EMB) g_stats[i] = 0.f;
    if (i < NB * EMB) g_pool[i] = 0.f;
    if (i < NB) g_cnt[i] = 0.f;
    if (i < Nn) g_deg[i] = 0;
}
__global__ void k_hist(const int* __restrict__ ei) {
    int i = blockIdx.x * blockDim.x + threadIdx.x;
    if (i < Ee) atomicAdd(&g_deg[ei[Ee + i]], 1);
}
__global__ void k_scan1() {
    __shared__ int s[256];
    int t = threadIdx.x;
    int i = blockIdx.x * 256 + t;
    int v = (i < Nn) ? g_deg[i] : 0;
    s[t] = v;
    __syncthreads();
#pragma unroll
    for (int off = 1; off < 256; off <<= 1) {
        int add = (t >= off) ? s[t - off] : 0;
        __syncthreads();
        s[t] += add;
        __syncthreads();
    }
    if (i < Nn) g_rowstart[i + 1] = s[t];
    if (t == 255) g_bsum[blockIdx.x] = s[255];
}
__global__ void k_scan2() {
    __shared__ int s[256];
    int t = threadIdx.x;
    int v = (t < NBLK_SCAN) ? g_bsum[t] : 0;
    s[t] = v;
    __syncthreads();
#pragma unroll
    for (int off = 1; off < 256; off <<= 1) {
        int add = (t >= off) ? s[t - off] : 0;
        __syncthreads();
        s[t] += add;
        __syncthreads();
    }
    if (t < NBLK_SCAN) g_boff[t] = s[t] - v;   // exclusive
}
__global__ void k_scan3() {
    int i = blockIdx.x * blockDim.x + threadIdx.x;
    if (i < Nn) {
        int v = g_rowstart[i + 1] + g_boff[i >> 8];
        g_rowstart[i + 1] = v;
        g_cursor[i] = v - g_deg[i];
    }
    if (i == 0) g_rowstart[0] = 0;
}
__global__ void k_fill(const int* __restrict__ ei) {
    int i = blockIdx.x * blockDim.x + threadIdx.x;
    if (i < Ee) {
        int d = ei[Ee + i];
        int pos = atomicAdd(&g_cursor[d], 1);
        g_elist[pos] = i;
    }
}

// ---- fused lin_in + pq(layer0): h = x@Win+bin ; p,q = h@W1[dup|src]+b1 -----
__global__ void k_linpq(const float* __restrict__ x, const float* __restrict__ w,
                        const float* __restrict__ b,
                        const float* __restrict__ w1, const float* __restrict__ b1) {
    __shared__ float ws[INDIM * EMB];
    __shared__ float xs[8][INDIM];
    __shared__ float wd[EMB * EMB];
    __shared__ float wsr[EMB * EMB];
    __shared__ float hs[8][EMB];
    int tx = threadIdx.x, ty = threadIdx.y;
    int tid = ty * 32 + tx;
    for (int i = tid; i < INDIM * EMB; i += 256) ws[i] = w[i];
    for (int i = tid; i < EMB * EMB; i += 256) { wd[i] = w1[i]; wsr[i] = w1[EMB * EMB + i]; }
    int base = blockIdx.x * 8;
    for (int i = tid; i < 8 * INDIM; i += 256) {
        int nloc = i >> 7, k = i & 127;
        xs[nloc][k] = x[(base + nloc) * INDIM + k];
    }
    __syncthreads();
    float acc = b[tx];
#pragma unroll 8
    for (int k = 0; k < INDIM; k++) acc = fmaf(xs[ty][k], ws[k * EMB + tx], acc);
    int n = base + ty;
    g_h[n * EMB + tx] = acc;
    hs[ty][tx] = acc;
    __syncthreads();
    float ap = b1[tx], aq = 0.f;
#pragma unroll
    for (int k = 0; k < EMB; k++) {
        float hv = hs[ty][k];
        ap = fmaf(hv, wd[k * EMB + tx], ap);
        aq = fmaf(hv, wsr[k * EMB + tx], aq);
    }
    g_p[n * EMB + tx] = ap;
    g_q[n * EMB + tx] = aq;
}

// ---- fused u3(prev layer) + pq(this layer) ---------------------------------
__global__ void k_u3pq(const float* __restrict__ w1, const float* __restrict__ b1,
                       const float* __restrict__ g2, const float* __restrict__ be2,
                       int prev) {
    __shared__ float wd[EMB * EMB];
    __shared__ float wsr[EMB * EMB];
    __shared__ float hs[8][EMB];
    int tx = threadIdx.x, ty = threadIdx.y;
    int tid = ty * 32 + tx;
    for (int i = tid; i < EMB * EMB; i += 256) { wd[i] = w1[i]; wsr[i] = w1[EMB * EMB + i]; }
    float s1 = g_stats[STAT_IDX(prev, 3, 0, tx)];
    float s2 = g_stats[STAT_IDX(prev, 3, 1, tx)];
    float mu = s1 * (1.f / Nn);
    float var = s2 * (1.f / Nn) - mu * mu;
    float rs = rsqrtf(var + EPS_BN);
    float sc = rs * g2[tx];
    float sh = be2[tx] - mu * sc;
    int base = blockIdx.x * 8;
    int n = base + ty;
    float hv = g_h[n * EMB + tx] + fmaxf(fmaf(g_y4[n * EMB + tx], sc, sh), 0.f);
    g_h[n * EMB + tx] = hv;
    hs[ty][tx] = hv;
    __syncthreads();
    float ap = b1[tx], aq = 0.f;
#pragma unroll
    for (int k = 0; k < EMB; k++) {
        float h2 = hs[ty][k];
        ap = fmaf(h2, wd[k * EMB + tx], ap);
        aq = fmaf(h2, wsr[k * EMB + tx], aq);
    }
    g_p[n * EMB + tx] = ap;
    g_q[n * EMB + tx] = aq;
}

// ---- E1: y1 = p[dst]+q[src]+ea@Wc -> g_yh (original order); stats stage 0 --
__global__ void __launch_bounds__(256) k_e1(const int* __restrict__ ei,
                     const float* __restrict__ ea,
                     const float* __restrict__ wc, int layer) {
    __shared__ float4 s_w[64];      // [k][cg]
    __shared__ float s_sum[EMB], s_ss[EMB];
    int tid = threadIdx.x;
    if (tid < 64) s_w[tid] = *(const float4*)(wc + (tid >> 3) * EMB + (tid & 7) * 4);
    if (tid < EMB) { s_sum[tid] = 0.f; s_ss[tid] = 0.f; }
    __syncthreads();
    int lane = tid & 31;
    int es = lane >> 3, cg = lane & 7, c0 = cg * 4;
    int nw = gridDim.x * (blockDim.x >> 5);
    int qd = blockIdx.x * (blockDim.x >> 5) + (tid >> 5);
    float4 sum = make_float4(0, 0, 0, 0), ss = make_float4(0, 0, 0, 0);
    const int NQ = Ee / 4;
    int s_nxt = 0, d_nxt = 0;
    if (qd < NQ) {
        int e = qd * 4 + es;
        s_nxt = ei[e];
        d_nxt = ei[Ee + e];
    }
    while (qd < NQ) {
        int e = qd * 4 + es;
        int s = s_nxt, d = d_nxt;
        int qn = qd + nw;
        if (qn < NQ) {
            int e2 = qn * 4 + es;
            s_nxt = ei[e2];
            d_nxt = ei[Ee + e2];
        }
        float4 pv = *(const float4*)(g_p + d * EMB + c0);
        float4 qv = *(const float4*)(g_q + s * EMB + c0);
        const float4* eap = (const float4*)(ea + (size_t)e * ED);
        float4 e0 = eap[0], e1v = eap[1];
        float4 y = f4add(pv, qv);
        f4fma(y, e0.x, s_w[0 * 8 + cg]); f4fma(y, e0.y, s_w[1 * 8 + cg]);
        f4fma(y, e0.z, s_w[2 * 8 + cg]); f4fma(y, e0.w, s_w[3 * 8 + cg]);
        f4fma(y, e1v.x, s_w[4 * 8 + cg]); f4fma(y, e1v.y, s_w[5 * 8 + cg]);
        f4fma(y, e1v.z, s_w[6 * 8 + cg]); f4fma(y, e1v.w, s_w[7 * 8 + cg]);
        store_h4(g_yh + (size_t)e * EMB + c0, y);
        sum = f4add(sum, y);
        ss.x = fmaf(y.x, y.x, ss.x); ss.y = fmaf(y.y, y.y, ss.y);
        ss.z = fmaf(y.z, y.z, ss.z); ss.w = fmaf(y.w, y.w, ss.w);
        qd = qn;
    }
    stats_warp_to_shared(sum, ss, lane, c0, s_sum, s_ss);
    __syncthreads();
    if (tid < EMB) {
        atomicAdd(&g_stats[STAT_IDX(layer, 0, 0, tid)], s_sum[tid]);
        atomicAdd(&g_stats[STAT_IDX(layer, 0, 1, tid)], s_ss[tid]);
    }
}

// ---- E2 (streaming): m1 = relu(bn(y1)); y2 = m1@W2+b2 in place; stats 1 ----
__global__ void __launch_bounds__(256) k_e2(const float* __restrict__ w2,
                     const float* __restrict__ b2,
                     const float* __restrict__ g1, const float* __restrict__ be1, int layer) {
    __shared__ float s_w2[EMB * EMB];
    __shared__ float s_sum[EMB], s_ss[EMB];
    int tid = threadIdx.x;
    for (int i = tid; i < EMB * EMB; i += 256) s_w2[i] = w2[i];
    if (tid < EMB) { s_sum[tid] = 0.f; s_ss[tid] = 0.f; }
    __syncthreads();
    int lane = tid & 31;
    int es = lane >> 3, cg = lane & 7, c0 = cg * 4, base = lane & 24;
    float sc[4], sh[4];
    bn_coeffs(layer, 0, 1.f / Ee, g1, be1, c0, sc, sh);
    float4 bb = *(const float4*)(b2 + c0);
    const float4* w2v = (const float4*)s_w2;
    int nw = gridDim.x * (blockDim.x >> 5);
    int gw = blockIdx.x * (blockDim.x >> 5) + (tid >> 5);
    float4 sum = make_float4(0, 0, 0, 0), ssq = make_float4(0, 0, 0, 0);
    for (int qd = gw; qd < Ee / 4; qd += nw) {
        int e = qd * 4 + es;
        float4 y1 = load_h4(g_yh + (size_t)e * EMB + c0);
        float m[4];
        m[0] = fmaxf(fmaf(y1.x, sc[0], sh[0]), 0.f);
        m[1] = fmaxf(fmaf(y1.y, sc[1], sh[1]), 0.f);
        m[2] = fmaxf(fmaf(y1.z, sc[2], sh[2]), 0.f);
        m[3] = fmaxf(fmaf(y1.w, sc[3], sh[3]), 0.f);
        float4 acc = bb;
#pragma unroll
        for (int j = 0; j < EMB; j++) {
            float mj = __shfl_sync(0xffffffffu, m[j & 3], base + (j >> 2));
            f4fma(acc, mj, w2v[j * 8 + cg]);
        }
        store_h4(g_yh + (size_t)e * EMB + c0, acc);
        sum = f4add(sum, acc);
        ssq.x = fmaf(acc.x, acc.x, ssq.x); ssq.y = fmaf(acc.y, acc.y, ssq.y);
        ssq.z = fmaf(acc.z, acc.z, ssq.z); ssq.w = fmaf(acc.w, acc.w, ssq.w);
    }
    stats_warp_to_shared(sum, ssq, lane, c0, s_sum, s_ss);
    __syncthreads();
    if (tid < EMB) {
        atomicAdd(&g_stats[STAT_IDX(layer, 1, 0, tid)], s_sum[tid]);
        atomicAdd(&g_stats[STAT_IDX(layer, 1, 1, tid)], s_ss[tid]);
    }
}

// ---- fused E3+U1: aggr via elist gathers (prefetched); y3; stats stage 2 ---
__global__ void __launch_bounds__(256) k_e3u1(const float* __restrict__ w,
                       const float* __restrict__ b,
                       const float* __restrict__ g2, const float* __restrict__ be2,
                       int layer) {
    __shared__ float sw[2 * EMB * EMB];
    __shared__ float s_sum[EMB], s_ss[EMB];
    int tid = threadIdx.x;
    for (int i = tid; i < 2 * EMB * EMB; i += 256) sw[i] = w[i];
    if (tid < EMB) { s_sum[tid] = 0.f; s_ss[tid] = 0.f; }
    __syncthreads();
    int lane = tid & 31;
    int es = lane >> 3, cg = lane & 7, c0 = cg * 4, base = lane & 24;
    float4 sum = make_float4(0, 0, 0, 0), ssq = make_float4(0, 0, 0, 0);

    int quad = blockIdx.x * 8 + (tid >> 5);
    if (quad * 4 < Nn) {
        float sc[4], sh[4];
        bn_coeffs(layer, 1, 1.f / Ee, g2, be2, c0, sc, sh);
        int n = quad * 4 + es;
        int rs = g_rowstart[n], re = g_rowstart[n + 1];
        float4 ag = make_float4(0, 0, 0, 0);
        int e_nxt = (rs < re) ? g_elist[rs] : 0;
        for (int i = rs; i < re; i++) {
            int e = e_nxt;
            if (i + 1 < re) e_nxt = g_elist[i + 1];
            float4 y = load_h4(g_yh + (size_t)e * EMB + c0);
            ag.x += fmaxf(fmaf(y.x, sc[0], sh[0]), 0.f);
            ag.y += fmaxf(fmaf(y.y, sc[1], sh[1]), 0.f);
            ag.z += fmaxf(fmaf(y.z, sc[2], sh[2]), 0.f);
            ag.w += fmaxf(fmaf(y.w, sc[3], sh[3]), 0.f);
        }
        float4 h4 = *(const float4*)(g_h + n * EMB + c0);
        float hr[4] = {h4.x, h4.y, h4.z, h4.w};
        float ar[4] = {ag.x, ag.y, ag.z, ag.w};
        const float4* swv = (const float4*)sw;
        float4 acc = *(const float4*)(b + c0);
#pragma unroll
        for (int j = 0; j < EMB; j++) {
            float hj = __shfl_sync(0xffffffffu, hr[j & 3], base + (j >> 2));
            f4fma(acc, hj, swv[j * 8 + cg]);
        }
#pragma unroll
        for (int j = 0; j < EMB; j++) {
            float aj = __shfl_sync(0xffffffffu, ar[j & 3], base + (j >> 2));
            f4fma(acc, aj, swv[(EMB + j) * 8 + cg]);
        }
        *(float4*)(g_y3 + n * EMB + c0) = acc;
        sum = acc;
        ssq.x = acc.x * acc.x; ssq.y = acc.y * acc.y;
        ssq.z = acc.z * acc.z; ssq.w = acc.w * acc.w;
    }
    stats_warp_to_shared(sum, ssq, lane, c0, s_sum, s_ss);
    __syncthreads();
    if (tid < EMB) {
        atomicAdd(&g_stats[STAT_IDX(layer, 2, 0, tid)], s_sum[tid]);
        atomicAdd(&g_stats[STAT_IDX(layer, 2, 1, tid)], s_ss[tid]);
    }
}

// ---------------- U2: r = relu(bn(y3)) ; y4 = r@Wu2+b ; stats stage 3 -------
__global__ void k_u2(const float* __restrict__ w2, const float* __restrict__ b2,
                     const float* __restrict__ g1, const float* __restrict__ be1, int layer) {
    __shared__ float s_w2[EMB * EMB];
    __shared__ float s_sum[EMB], s_ss[EMB];
    int tid = threadIdx.x;
    for (int i = tid; i < EMB * EMB; i += 256) s_w2[i] = w2[i];
    if (tid < EMB) { s_sum[tid] = 0.f; s_ss[tid] = 0.f; }
    __syncthreads();
    int lane = tid & 31;
    int es = lane >> 3, cg = lane & 7, c0 = cg * 4, base = lane & 24;
    float sc[4], sh[4];
    bn_coeffs(layer, 2, 1.f / Nn, g1, be1, c0, sc, sh);
    float4 bb = *(const float4*)(b2 + c0);
    const float4* w2v = (const float4*)s_w2;
    int nw = gridDim.x * (blockDim.x >> 5);
    int gw = blockIdx.x * (blockDim.x >> 5) + (tid >> 5);
    float4 sum = make_float4(0, 0, 0, 0), ssq = make_float4(0, 0, 0, 0);
    for (int qd = gw; qd < Nn / 4; qd += nw) {
        int n = qd * 4 + es;
        float4 y1 = *(const float4*)(g_y3 + n * EMB + c0);
        float m[4];
        m[0] = fmaxf(fmaf(y1.x, sc[0], sh[0]), 0.f);
        m[1] = fmaxf(fmaf(y1.y, sc[1], sh[1]), 0.f);
        m[2] = fmaxf(fmaf(y1.z, sc[2], sh[2]), 0.f);
        m[3] = fmaxf(fmaf(y1.w, sc[3], sh[3]), 0.f);
        float4 acc = bb;
#pragma unroll
        for (int j = 0; j < EMB; j++) {
            float mj = __shfl_sync(0xffffffffu, m[j & 3], base + (j >> 2));
            f4fma(acc, mj, w2v[j * 8 + cg]);
        }
        *(float4*)(g_y4 + n * EMB + c0) = acc;
        sum = f4add(sum, acc);
        ssq.x = fmaf(acc.x, acc.x, ssq.x); ssq.y = fmaf(acc.y, acc.y, ssq.y);
        ssq.z = fmaf(acc.z, acc.z, ssq.z); ssq.w = fmaf(acc.w, acc.w, ssq.w);
    }
    stats_warp_to_shared(sum, ssq, lane, c0, s_sum, s_ss);
    __syncthreads();
    if (tid < EMB) {
        atomicAdd(&g_stats[STAT_IDX(layer, 3, 0, tid)], s_sum[tid]);
        atomicAdd(&g_stats[STAT_IDX(layer, 3, 1, tid)], s_ss[tid]);
    }
}

// ---- final layer: h_final = h + relu(bn(y4)); pool atomics -----------------
__global__ void k_u3pool(const int* __restrict__ batch,
                         const float* __restrict__ g2, const float* __restrict__ be2,
                         int layer) {
    int idx = blockIdx.x * blockDim.x + threadIdx.x;
    if (idx >= Nn * 8) return;
    int n = idx >> 3, cg = idx & 7, c0 = cg * 4;
    float sc[4], sh[4];
    bn_coeffs(layer, 3, 1.f / Nn, g2, be2, c0, sc, sh);
    float4 y = *(const float4*)(g_y4 + n * EMB + c0);
    float4 h = *(const float4*)(g_h + n * EMB + c0);
    h.x += fmaxf(fmaf(y.x, sc[0], sh[0]), 0.f);
    h.y += fmaxf(fmaf(y.y, sc[1], sh[1]), 0.f);
    h.z += fmaxf(fmaf(y.z, sc[2], sh[2]), 0.f);
    h.w += fmaxf(fmaf(y.w, sc[3], sh[3]), 0.f);
    int b = batch[n];
    float* pp = g_pool + b * EMB + c0;
    atomicAdd(pp + 0, h.x); atomicAdd(pp + 1, h.y);
    atomicAdd(pp + 2, h.z); atomicAdd(pp + 3, h.w);
    if (cg == 0) atomicAdd(&g_cnt[b], 1.0f);
}

__global__ void k_pred(const float* __restrict__ pw, const float* __restrict__ pb,
                       float* __restrict__ out) {
    int t = threadIdx.x;
    if (t >= NB * NOUT) return;
    int b = t / NOUT, o = t % NOUT;
    float inv = 1.f / fmaxf(g_cnt[b], 1.f);
    float s = 0.f;
#pragma unroll
    for (int j = 0; j < EMB; j++) s = fmaf(g_pool[b * EMB + j], pw[j * NOUT + o], s);
    out[t] = pb[o] + s * inv;
}

// ---------------- launch -----------------------------------------------------
extern "C" void kernel_launch(void* const* d_in, const int* in_sizes, int n_in,
                              void* d_out, int out_size) {
    const float *x, *edge_attr, *lin_in_w, *lin_in_b;
    const float *msg_w1, *msg_b1, *msg_g1, *msg_be1, *msg_w2, *msg_b2, *msg_g2, *msg_be2;
    const float *upd_w1, *upd_b1, *upd_g1, *upd_be1, *upd_w2, *upd_b2, *upd_g2, *upd_be2;
    const float *pred_w, *pred_b;
    const int *edge_idx, *batch;

    if (in_sizes[1] == 2 * Ee) {
        x        = (const float*)d_in[0];
        edge_idx = (const int*)  d_in[1];
        edge_attr= (const float*)d_in[2];
        batch    = (const int*)  d_in[3];
        lin_in_w = (const float*)d_in[4];
        lin_in_b = (const float*)d_in[5];
        msg_w1   = (const float*)d_in[6];
        msg_b1   = (const float*)d_in[7];
        msg_g1   = (const float*)d_in[8];
        msg_be1  = (const float*)d_in[9];
        msg_w2   = (const float*)d_in[10];
        msg_b2   = (const float*)d_in[11];
        msg_g2   = (const float*)d_in[12];
        msg_be2  = (const float*)d_in[13];
        upd_w1   = (const float*)d_in[14];
        upd_b1   = (const float*)d_in[15];
        upd_g1   = (const float*)d_in[16];
        upd_be1  = (const float*)d_in[17];
        upd_w2   = (const float*)d_in[18];
        upd_b2   = (const float*)d_in[19];
        upd_g2   = (const float*)d_in[20];
        upd_be2  = (const float*)d_in[21];
        pred_w   = (const float*)d_in[22];
        pred_b   = (const float*)d_in[23];
    } else {
        x        = (const float*)d_in[0];
        edge_attr= (const float*)d_in[1];
        lin_in_w = (const float*)d_in[2];
        lin_in_b = (const float*)d_in[3];
        msg_w1   = (const float*)d_in[4];
        msg_b1   = (const float*)d_in[5];
        msg_g1   = (const float*)d_in[6];
        msg_be1  = (const float*)d_in[7];
        msg_w2   = (const float*)d_in[8];
        msg_b2   = (const float*)d_in[9];
        msg_g2   = (const float*)d_in[10];
        msg_be2  = (const float*)d_in[11];
        upd_w1   = (const float*)d_in[12];
        upd_b1   = (const float*)d_in[13];
        upd_g1   = (const float*)d_in[14];
        upd_be1  = (const float*)d_in[15];
        upd_w2   = (const float*)d_in[16];
        upd_b2   = (const float*)d_in[17];
        upd_g2   = (const float*)d_in[18];
        upd_be2  = (const float*)d_in[19];
        pred_w   = (const float*)d_in[20];
        pred_b   = (const float*)d_in[21];
        edge_idx = (const int*)  d_in[22];
        batch    = (const int*)  d_in[23];
    }
    float* out = (float*)d_out;

    // exact-wave grids for the big edge kernels (host-side query; capture-safe)
    int b1 = 8, b2 = 8;
    cudaOccupancyMaxActiveBlocksPerMultiprocessor(&b1, k_e1, 256, 0);
    cudaOccupancyMaxActiveBlocksPerMultiprocessor(&b2, k_e2, 256, 0);
    int grid_e1 = b1 * NSM, grid_e2 = b2 * NSM;

    // Launch order puts k_e2 at capture slot (4th launch):
    // 0: zero, 1: linpq, 2: e1(l0), 3: e2(l0), then CSR build, then rest.
    k_zero_once<<<NBLK_SCAN, 256>>>();
    k_linpq<<<Nn / 8, dim3(32, 8)>>>(x, lin_in_w, lin_in_b, msg_w1, msg_b1);
    {
        const float* w1 = msg_w1;
        k_e1<<<grid_e1, 256>>>(edge_idx, edge_attr, w1 + 2 * EMB * EMB, 0);
        k_e2<<<grid_e2, 256>>>(msg_w2, msg_b2, msg_g1, msg_be1, 0);
    }
    // CSR build (needed only by e3u1)
    k_hist<<<(Ee + 255) / 256, 256>>>(edge_idx);
    k_scan1<<<NBLK_SCAN, 256>>>();
    k_scan2<<<1, 256>>>();
    k_scan3<<<NBLK_SCAN, 256>>>();
    k_fill<<<(Ee + 255) / 256, 256>>>(edge_idx);

    for (int l = 0; l < NL; l++) {
        const float* w1 = msg_w1 + l * (2 * EMB + ED) * EMB;
        if (l > 0) {
            k_u3pq<<<Nn / 8, dim3(32, 8)>>>(w1, msg_b1 + l * EMB,
                                            upd_g2 + (l - 1) * EMB, upd_be2 + (l - 1) * EMB,
                                            l - 1);
            k_e1<<<grid_e1, 256>>>(edge_idx, edge_attr, w1 + 2 * EMB * EMB, l);
            k_e2<<<grid_e2, 256>>>(msg_w2 + l * EMB * EMB, msg_b2 + l * EMB,
                                   msg_g1 + l * EMB, msg_be1 + l * EMB, l);
        }
        k_e3u1<<<(Nn / 4 + 7) / 8, 256>>>(upd_w1 + l * 2 * EMB * EMB, upd_b1 + l * EMB,
                                          msg_g2 + l * EMB, msg_be2 + l * EMB, l);
        k_u2<<<1184, 256>>>(upd_w2 + l * EMB * EMB, upd_b2 + l * EMB,
                            upd_g1 + l * EMB, upd_be1 + l * EMB, l);
    }
    k_u3pool<<<(Nn * 8 + 255) / 256, 256>>>(batch, upd_g2 + (NL - 1) * EMB,
                                            upd_be2 + (NL - 1) * EMB, NL - 1);
    k_pred<<<1, NB * NOUT>>>(pred_w, pred_b, out);
}

// round 11
// speedup vs baseline: 1.3022x; 1.2900x over previous
#include <cuda_runtime.h>
#include <cuda_fp16.h>

#define Nn    50000
#define Ee    800000
#define INDIM 128
#define EMB   32
#define ED    8
#define NL    4
#define NB    64
#define NOUT  10
#define EPS_BN 1e-5f
#define NBLK_SCAN 196   // ceil(Nn/256)
#define NSM   148

// ---------------- scratch (device globals) ----------------------------------
__device__ __align__(16) float  g_h[Nn * EMB];
__device__ __align__(16) float  g_p[Nn * EMB];
__device__ __align__(16) float  g_q[Nn * EMB];
__device__ __align__(16) float  g_y3[Nn * EMB];
__device__ __align__(16) float  g_y4[Nn * EMB];
__device__ __align__(16) __half g_yh[(size_t)Ee * EMB];   // y1/y2, fp16, original edge order
__device__ __align__(16) float  g_stats[NL * 4 * 2 * EMB];
__device__ __align__(16) float  g_pool[NB * EMB];
__device__ __align__(16) float  g_cnt[NB];
// CSR (built once per launch; dst is launch-invariant)
__device__ int g_deg[Nn];
__device__ int g_rowstart[Nn + 1];
__device__ int g_cursor[Nn];
__device__ int g_elist[Ee];
__device__ int g_bsum[NBLK_SCAN];
__device__ int g_boff[NBLK_SCAN];

#define STAT_IDX(l, stage, which, c) ((((l) * 4 + (stage)) * 2 + (which)) * EMB + (c))

// ---------------- helpers ---------------------------------------------------
__device__ __forceinline__ float4 f4add(float4 a, float4 b) {
    return make_float4(a.x + b.x, a.y + b.y, a.z + b.z, a.w + b.w);
}
__device__ __forceinline__ void f4fma(float4& a, float s, float4 w) {
    a.x = fmaf(s, w.x, a.x); a.y = fmaf(s, w.y, a.y);
    a.z = fmaf(s, w.z, a.z); a.w = fmaf(s, w.w, a.w);
}
__device__ __forceinline__ void store_h4(__half* p, float4 v) {
    union { __half2 h[2]; uint2 u; } cv;
    cv.h[0] = __float22half2_rn(make_float2(v.x, v.y));
    cv.h[1] = __float22half2_rn(make_float2(v.z, v.w));
    *(uint2*)p = cv.u;
}
__device__ __forceinline__ float4 load_h4(const __half* p) {
    union { uint2 u; __half2 h[2]; } cv;
    cv.u = *(const uint2*)p;
    float2 a = __half22float2(cv.h[0]);
    float2 b = __half22float2(cv.h[1]);
    return make_float4(a.x, a.y, b.x, b.y);
}

__device__ __forceinline__ void stats_warp_to_shared(float4 sum, float4 ss, int lane,
                                                     int c0, float* s_sum, float* s_ss) {
#pragma unroll
    for (int off = 8; off < 32; off <<= 1) {
        sum.x += __shfl_xor_sync(0xffffffffu, sum.x, off);
        sum.y += __shfl_xor_sync(0xffffffffu, sum.y, off);
        sum.z += __shfl_xor_sync(0xffffffffu, sum.z, off);
        sum.w += __shfl_xor_sync(0xffffffffu, sum.w, off);
        ss.x  += __shfl_xor_sync(0xffffffffu, ss.x, off);
        ss.y  += __shfl_xor_sync(0xffffffffu, ss.y, off);
        ss.z  += __shfl_xor_sync(0xffffffffu, ss.z, off);
        ss.w  += __shfl_xor_sync(0xffffffffu, ss.w, off);
    }
    if (lane < 8) {
        atomicAdd(&s_sum[c0 + 0], sum.x); atomicAdd(&s_sum[c0 + 1], sum.y);
        atomicAdd(&s_sum[c0 + 2], sum.z); atomicAdd(&s_sum[c0 + 3], sum.w);
        atomicAdd(&s_ss[c0 + 0], ss.x);   atomicAdd(&s_ss[c0 + 1], ss.y);
        atomicAdd(&s_ss[c0 + 2], ss.z);   atomicAdd(&s_ss[c0 + 3], ss.w);
    }
}

__device__ __forceinline__ void bn_coeffs(int l, int stage, float inv_n,
                                          const float* __restrict__ gamma,
                                          const float* __restrict__ beta,
                                          int c0, float sc[4], float sh[4]) {
#pragma unroll
    for (int i = 0; i < 4; i++) {
        int c = c0 + i;
        float s1 = g_stats[STAT_IDX(l, stage, 0, c)];
        float s2 = g_stats[STAT_IDX(l, stage, 1, c)];
        float mu = s1 * inv_n;
        float var = s2 * inv_n - mu * mu;
        float rs = rsqrtf(var + EPS_BN);
        sc[i] = rs * gamma[c];
        sh[i] = beta[c] - mu * sc[i];
    }
}

// ---------------- init + CSR build ------------------------------------------
__global__ void k_zero_once() {
    int i = blockIdx.x * blockDim.x + threadIdx.x;
    if (i < NL * 4 * 2 * EMB) g_stats[i] = 0.f;
    if (i < NB * EMB) g_pool[i] = 0.f;
    if (i < NB) g_cnt[i] = 0.f;
    if (i < Nn) g_deg[i] = 0;
}
__global__ void k_hist(const int* __restrict__ ei) {
    int i = blockIdx.x * blockDim.x + threadIdx.x;
    if (i < Ee) atomicAdd(&g_deg[ei[Ee + i]], 1);
}
__global__ void k_scan1() {
    __shared__ int s[256];
    int t = threadIdx.x;
    int i = blockIdx.x * 256 + t;
    int v = (i < Nn) ? g_deg[i] : 0;
    s[t] = v;
    __syncthreads();
#pragma unroll
    for (int off = 1; off < 256; off <<= 1) {
        int add = (t >= off) ? s[t - off] : 0;
        __syncthreads();
        s[t] += add;
        __syncthreads();
    }
    if (i < Nn) g_rowstart[i + 1] = s[t];
    if (t == 255) g_bsum[blockIdx.x] = s[255];
}
__global__ void k_scan2() {
    __shared__ int s[256];
    int t = threadIdx.x;
    int v = (t < NBLK_SCAN) ? g_bsum[t] : 0;
    s[t] = v;
    __syncthreads();
#pragma unroll
    for (int off = 1; off < 256; off <<= 1) {
        int add = (t >= off) ? s[t - off] : 0;
        __syncthreads();
        s[t] += add;
        __syncthreads();
    }
    if (t < NBLK_SCAN) g_boff[t] = s[t] - v;   // exclusive
}
__global__ void k_scan3() {
    int i = blockIdx.x * blockDim.x + threadIdx.x;
    if (i < Nn) {
        int v = g_rowstart[i + 1] + g_boff[i >> 8];
        g_rowstart[i + 1] = v;
        g_cursor[i] = v - g_deg[i];
    }
    if (i == 0) g_rowstart[0] = 0;
}
__global__ void k_fill(const int* __restrict__ ei) {
    int i = blockIdx.x * blockDim.x + threadIdx.x;
    if (i < Ee) {
        int d = ei[Ee + i];
        int pos = atomicAdd(&g_cursor[d], 1);
        g_elist[pos] = i;
    }
}

// ---- fused lin_in + pq(layer0) ----------------------------------------------
__global__ void k_linpq(const float* __restrict__ x, const float* __restrict__ w,
                        const float* __restrict__ b,
                        const float* __restrict__ w1, const float* __restrict__ b1) {
    __shared__ float ws[INDIM * EMB];
    __shared__ float xs[8][INDIM];
    __shared__ float wd[EMB * EMB];
    __shared__ float wsr[EMB * EMB];
    __shared__ float hs[8][EMB];
    int tx = threadIdx.x, ty = threadIdx.y;
    int tid = ty * 32 + tx;
    for (int i = tid; i < INDIM * EMB; i += 256) ws[i] = w[i];
    for (int i = tid; i < EMB * EMB; i += 256) { wd[i] = w1[i]; wsr[i] = w1[EMB * EMB + i]; }
    int base = blockIdx.x * 8;
    for (int i = tid; i < 8 * INDIM; i += 256) {
        int nloc = i >> 7, k = i & 127;
        xs[nloc][k] = x[(base + nloc) * INDIM + k];
    }
    __syncthreads();
    float acc = b[tx];
#pragma unroll 8
    for (int k = 0; k < INDIM; k++) acc = fmaf(xs[ty][k], ws[k * EMB + tx], acc);
    int n = base + ty;
    g_h[n * EMB + tx] = acc;
    hs[ty][tx] = acc;
    __syncthreads();
    float ap = b1[tx], aq = 0.f;
#pragma unroll
    for (int k = 0; k < EMB; k++) {
        float hv = hs[ty][k];
        ap = fmaf(hv, wd[k * EMB + tx], ap);
        aq = fmaf(hv, wsr[k * EMB + tx], aq);
    }
    g_p[n * EMB + tx] = ap;
    g_q[n * EMB + tx] = aq;
}

// ---- fused u3(prev layer) + pq(this layer) ---------------------------------
__global__ void k_u3pq(const float* __restrict__ w1, const float* __restrict__ b1,
                       const float* __restrict__ g2, const float* __restrict__ be2,
                       int prev) {
    __shared__ float wd[EMB * EMB];
    __shared__ float wsr[EMB * EMB];
    __shared__ float hs[8][EMB];
    int tx = threadIdx.x, ty = threadIdx.y;
    int tid = ty * 32 + tx;
    for (int i = tid; i < EMB * EMB; i += 256) { wd[i] = w1[i]; wsr[i] = w1[EMB * EMB + i]; }
    float s1 = g_stats[STAT_IDX(prev, 3, 0, tx)];
    float s2 = g_stats[STAT_IDX(prev, 3, 1, tx)];
    float mu = s1 * (1.f / Nn);
    float var = s2 * (1.f / Nn) - mu * mu;
    float rs = rsqrtf(var + EPS_BN);
    float sc = rs * g2[tx];
    float sh = be2[tx] - mu * sc;
    int base = blockIdx.x * 8;
    int n = base + ty;
    float hv = g_h[n * EMB + tx] + fmaxf(fmaf(g_y4[n * EMB + tx], sc, sh), 0.f);
    g_h[n * EMB + tx] = hv;
    hs[ty][tx] = hv;
    __syncthreads();
    float ap = b1[tx], aq = 0.f;
#pragma unroll
    for (int k = 0; k < EMB; k++) {
        float h2 = hs[ty][k];
        ap = fmaf(h2, wd[k * EMB + tx], ap);
        aq = fmaf(h2, wsr[k * EMB + tx], aq);
    }
    g_p[n * EMB + tx] = ap;
    g_q[n * EMB + tx] = aq;
}

// ---- E1: y1 = p[dst]+q[src]+ea@Wc -> g_yh (original order); stats stage 0 --
__global__ void __launch_bounds__(256) k_e1(const int* __restrict__ ei,
                     const float* __restrict__ ea,
                     const float* __restrict__ wc, int layer) {
    __shared__ float4 s_w[64];      // [k][cg]
    __shared__ float s_sum[EMB], s_ss[EMB];
    int tid = threadIdx.x;
    if (tid < 64) s_w[tid] = *(const float4*)(wc + (tid >> 3) * EMB + (tid & 7) * 4);
    if (tid < EMB) { s_sum[tid] = 0.f; s_ss[tid] = 0.f; }
    __syncthreads();
    int lane = tid & 31;
    int es = lane >> 3, cg = lane & 7, c0 = cg * 4;
    int nw = gridDim.x * (blockDim.x >> 5);
    int qd = blockIdx.x * (blockDim.x >> 5) + (tid >> 5);
    float4 sum = make_float4(0, 0, 0, 0), ss = make_float4(0, 0, 0, 0);
    const int NQ = Ee / 4;
    int s_nxt = 0, d_nxt = 0;
    if (qd < NQ) {
        int e = qd * 4 + es;
        s_nxt = ei[e];
        d_nxt = ei[Ee + e];
    }
    while (qd < NQ) {
        int e = qd * 4 + es;
        int s = s_nxt, d = d_nxt;
        int qn = qd + nw;
        if (qn < NQ) {
            int e2 = qn * 4 + es;
            s_nxt = ei[e2];
            d_nxt = ei[Ee + e2];
        }
        float4 pv = *(const float4*)(g_p + d * EMB + c0);
        float4 qv = *(const float4*)(g_q + s * EMB + c0);
        const float4* eap = (const float4*)(ea + (size_t)e * ED);
        float4 e0 = eap[0], e1v = eap[1];
        float4 y = f4add(pv, qv);
        f4fma(y, e0.x, s_w[0 * 8 + cg]); f4fma(y, e0.y, s_w[1 * 8 + cg]);
        f4fma(y, e0.z, s_w[2 * 8 + cg]); f4fma(y, e0.w, s_w[3 * 8 + cg]);
        f4fma(y, e1v.x, s_w[4 * 8 + cg]); f4fma(y, e1v.y, s_w[5 * 8 + cg]);
        f4fma(y, e1v.z, s_w[6 * 8 + cg]); f4fma(y, e1v.w, s_w[7 * 8 + cg]);
        store_h4(g_yh + (size_t)e * EMB + c0, y);
        sum = f4add(sum, y);
        ss.x = fmaf(y.x, y.x, ss.x); ss.y = fmaf(y.y, y.y, ss.y);
        ss.z = fmaf(y.z, y.z, ss.z); ss.w = fmaf(y.w, y.w, ss.w);
        qd = qn;
    }
    stats_warp_to_shared(sum, ss, lane, c0, s_sum, s_ss);
    __syncthreads();
    if (tid < EMB) {
        atomicAdd(&g_stats[STAT_IDX(layer, 0, 0, tid)], s_sum[tid]);
        atomicAdd(&g_stats[STAT_IDX(layer, 0, 1, tid)], s_ss[tid]);
    }
}

// ---- E2 (register-blocked): each lane carries 4 quads per W2 fetch ---------
// m1 = relu(bn(y1)); y2 = m1@W2+b2 in place; stats stage 1.
__global__ void __launch_bounds__(256) k_e2(const float* __restrict__ w2,
                     const float* __restrict__ b2,
                     const float* __restrict__ g1, const float* __restrict__ be1, int layer) {
    __shared__ float s_w2[EMB * EMB];
    __shared__ float s_sum[EMB], s_ss[EMB];
    int tid = threadIdx.x;
    for (int i = tid; i < EMB * EMB; i += 256) s_w2[i] = w2[i];
    if (tid < EMB) { s_sum[tid] = 0.f; s_ss[tid] = 0.f; }
    __syncthreads();
    int lane = tid & 31;
    int es = lane >> 3, cg = lane & 7, c0 = cg * 4, base = lane & 24;
    float sc[4], sh[4];
    bn_coeffs(layer, 0, 1.f / Ee, g1, be1, c0, sc, sh);
    float4 bb = *(const float4*)(b2 + c0);
    const float4* w2v = (const float4*)s_w2;
    int nw = gridDim.x * (blockDim.x >> 5);
    int gw = blockIdx.x * (blockDim.x >> 5) + (tid >> 5);
    float4 sum = make_float4(0, 0, 0, 0), ssq = make_float4(0, 0, 0, 0);
    const int NQ = Ee / 4;   // 200000, divisible by 4
    for (int q0 = gw * 4; q0 < NQ; q0 += nw * 4) {
        // load 4 quads' activations, compute m (all live in regs)
        float m[4][4];
        float4 acc[4];
#pragma unroll
        for (int k = 0; k < 4; k++) {
            int e = (q0 + k) * 4 + es;
            float4 y1 = load_h4(g_yh + (size_t)e * EMB + c0);
            m[k][0] = fmaxf(fmaf(y1.x, sc[0], sh[0]), 0.f);
            m[k][1] = fmaxf(fmaf(y1.y, sc[1], sh[1]), 0.f);
            m[k][2] = fmaxf(fmaf(y1.z, sc[2], sh[2]), 0.f);
            m[k][3] = fmaxf(fmaf(y1.w, sc[3], sh[3]), 0.f);
            acc[k] = bb;
        }
        // one W2 row fetch serves 4 quads (16 edges)
#pragma unroll
        for (int j = 0; j < EMB; j++) {
            float4 wv = w2v[j * 8 + cg];
#pragma unroll
            for (int k = 0; k < 4; k++) {
                float mj = __shfl_sync(0xffffffffu, m[k][j & 3], base + (j >> 2));
                f4fma(acc[k], mj, wv);
            }
        }
#pragma unroll
        for (int k = 0; k < 4; k++) {
            int e = (q0 + k) * 4 + es;
            store_h4(g_yh + (size_t)e * EMB + c0, acc[k]);
            sum = f4add(sum, acc[k]);
            ssq.x = fmaf(acc[k].x, acc[k].x, ssq.x);
            ssq.y = fmaf(acc[k].y, acc[k].y, ssq.y);
            ssq.z = fmaf(acc[k].z, acc[k].z, ssq.z);
            ssq.w = fmaf(acc[k].w, acc[k].w, ssq.w);
        }
    }
    stats_warp_to_shared(sum, ssq, lane, c0, s_sum, s_ss);
    __syncthreads();
    if (tid < EMB) {
        atomicAdd(&g_stats[STAT_IDX(layer, 1, 0, tid)], s_sum[tid]);
        atomicAdd(&g_stats[STAT_IDX(layer, 1, 1, tid)], s_ss[tid]);
    }
}

// ---- fused E3+U1: aggr via elist gathers (prefetched); y3; stats stage 2 ---
__global__ void __launch_bounds__(256) k_e3u1(const float* __restrict__ w,
                       const float* __restrict__ b,
                       const float* __restrict__ g2, const float* __restrict__ be2,
                       int layer) {
    __shared__ float sw[2 * EMB * EMB];
    __shared__ float s_sum[EMB], s_ss[EMB];
    int tid = threadIdx.x;
    for (int i = tid; i < 2 * EMB * EMB; i += 256) sw[i] = w[i];
    if (tid < EMB) { s_sum[tid] = 0.f; s_ss[tid] = 0.f; }
    __syncthreads();
    int lane = tid & 31;
    int es = lane >> 3, cg = lane & 7, c0 = cg * 4, base = lane & 24;
    float4 sum = make_float4(0, 0, 0, 0), ssq = make_float4(0, 0, 0, 0);

    int quad = blockIdx.x * 8 + (tid >> 5);
    if (quad * 4 < Nn) {
        float sc[4], sh[4];
        bn_coeffs(layer, 1, 1.f / Ee, g2, be2, c0, sc, sh);
        int n = quad * 4 + es;
        int rs = g_rowstart[n], re = g_rowstart[n + 1];
        float4 ag = make_float4(0, 0, 0, 0);
        int e_nxt = (rs < re) ? g_elist[rs] : 0;
        for (int i = rs; i < re; i++) {
            int e = e_nxt;
            if (i + 1 < re) e_nxt = g_elist[i + 1];
            float4 y = load_h4(g_yh + (size_t)e * EMB + c0);
            ag.x += fmaxf(fmaf(y.x, sc[0], sh[0]), 0.f);
            ag.y += fmaxf(fmaf(y.y, sc[1], sh[1]), 0.f);
            ag.z += fmaxf(fmaf(y.z, sc[2], sh[2]), 0.f);
            ag.w += fmaxf(fmaf(y.w, sc[3], sh[3]), 0.f);
        }
        float4 h4 = *(const float4*)(g_h + n * EMB + c0);
        float hr[4] = {h4.x, h4.y, h4.z, h4.w};
        float ar[4] = {ag.x, ag.y, ag.z, ag.w};
        const float4* swv = (const float4*)sw;
        float4 acc = *(const float4*)(b + c0);
#pragma unroll
        for (int j = 0; j < EMB; j++) {
            float hj = __shfl_sync(0xffffffffu, hr[j & 3], base + (j >> 2));
            f4fma(acc, hj, swv[j * 8 + cg]);
        }
#pragma unroll
        for (int j = 0; j < EMB; j++) {
            float aj = __shfl_sync(0xffffffffu, ar[j & 3], base + (j >> 2));
            f4fma(acc, aj, swv[(EMB + j) * 8 + cg]);
        }
        *(float4*)(g_y3 + n * EMB + c0) = acc;
        sum = acc;
        ssq.x = acc.x * acc.x; ssq.y = acc.y * acc.y;
        ssq.z = acc.z * acc.z; ssq.w = acc.w * acc.w;
    }
    stats_warp_to_shared(sum, ssq, lane, c0, s_sum, s_ss);
    __syncthreads();
    if (tid < EMB) {
        atomicAdd(&g_stats[STAT_IDX(layer, 2, 0, tid)], s_sum[tid]);
        atomicAdd(&g_stats[STAT_IDX(layer, 2, 1, tid)], s_ss[tid]);
    }
}

// ---------------- U2: r = relu(bn(y3)) ; y4 = r@Wu2+b ; stats stage 3 -------
__global__ void k_u2(const float* __restrict__ w2, const float* __restrict__ b2,
                     const float* __restrict__ g1, const float* __restrict__ be1, int layer) {
    __shared__ float s_w2[EMB * EMB];
    __shared__ float s_sum[EMB], s_ss[EMB];
    int tid = threadIdx.x;
    for (int i = tid; i < EMB * EMB; i += 256) s_w2[i] = w2[i];
    if (tid < EMB) { s_sum[tid] = 0.f; s_ss[tid] = 0.f; }
    __syncthreads();
    int lane = tid & 31;
    int es = lane >> 3, cg = lane & 7, c0 = cg * 4, base = lane & 24;
    float sc[4], sh[4];
    bn_coeffs(layer, 2, 1.f / Nn, g1, be1, c0, sc, sh);
    float4 bb = *(const float4*)(b2 + c0);
    const float4* w2v = (const float4*)s_w2;
    int nw = gridDim.x * (blockDim.x >> 5);
    int gw = blockIdx.x * (blockDim.x >> 5) + (tid >> 5);
    float4 sum = make_float4(0, 0, 0, 0), ssq = make_float4(0, 0, 0, 0);
    for (int qd = gw; qd < Nn / 4; qd += nw) {
        int n = qd * 4 + es;
        float4 y1 = *(const float4*)(g_y3 + n * EMB + c0);
        float m[4];
        m[0] = fmaxf(fmaf(y1.x, sc[0], sh[0]), 0.f);
        m[1] = fmaxf(fmaf(y1.y, sc[1], sh[1]), 0.f);
        m[2] = fmaxf(fmaf(y1.z, sc[2], sh[2]), 0.f);
        m[3] = fmaxf(fmaf(y1.w, sc[3], sh[3]), 0.f);
        float4 acc = bb;
#pragma unroll
        for (int j = 0; j < EMB; j++) {
            float mj = __shfl_sync(0xffffffffu, m[j & 3], base + (j >> 2));
            f4fma(acc, mj, w2v[j * 8 + cg]);
        }
        *(float4*)(g_y4 + n * EMB + c0) = acc;
        sum = f4add(sum, acc);
        ssq.x = fmaf(acc.x, acc.x, ssq.x); ssq.y = fmaf(acc.y, acc.y, ssq.y);
        ssq.z = fmaf(acc.z, acc.z, ssq.z); ssq.w = fmaf(acc.w, acc.w, ssq.w);
    }
    stats_warp_to_shared(sum, ssq, lane, c0, s_sum, s_ss);
    __syncthreads();
    if (tid < EMB) {
        atomicAdd(&g_stats[STAT_IDX(layer, 3, 0, tid)], s_sum[tid]);
        atomicAdd(&g_stats[STAT_IDX(layer, 3, 1, tid)], s_ss[tid]);
    }
}

// ---- final layer: h_final = h + relu(bn(y4)); pool atomics -----------------
__global__ void k_u3pool(const int* __restrict__ batch,
                         const float* __restrict__ g2, const float* __restrict__ be2,
                         int layer) {
    int idx = blockIdx.x * blockDim.x + threadIdx.x;
    if (idx >= Nn * 8) return;
    int n = idx >> 3, cg = idx & 7, c0 = cg * 4;
    float sc[4], sh[4];
    bn_coeffs(layer, 3, 1.f / Nn, g2, be2, c0, sc, sh);
    float4 y = *(const float4*)(g_y4 + n * EMB + c0);
    float4 h = *(const float4*)(g_h + n * EMB + c0);
    h.x += fmaxf(fmaf(y.x, sc[0], sh[0]), 0.f);
    h.y += fmaxf(fmaf(y.y, sc[1], sh[1]), 0.f);
    h.z += fmaxf(fmaf(y.z, sc[2], sh[2]), 0.f);
    h.w += fmaxf(fmaf(y.w, sc[3], sh[3]), 0.f);
    int b = batch[n];
    float* pp = g_pool + b * EMB + c0;
    atomicAdd(pp + 0, h.x); atomicAdd(pp + 1, h.y);
    atomicAdd(pp + 2, h.z); atomicAdd(pp + 3, h.w);
    if (cg == 0) atomicAdd(&g_cnt[b], 1.0f);
}

__global__ void k_pred(const float* __restrict__ pw, const float* __restrict__ pb,
                       float* __restrict__ out) {
    int t = threadIdx.x;
    if (t >= NB * NOUT) return;
    int b = t / NOUT, o = t % NOUT;
    float inv = 1.f / fmaxf(g_cnt[b], 1.f);
    float s = 0.f;
#pragma unroll
    for (int j = 0; j < EMB; j++) s = fmaf(g_pool[b * EMB + j], pw[j * NOUT + o], s);
    out[t] = pb[o] + s * inv;
}

// ---------------- launch -----------------------------------------------------
extern "C" void kernel_launch(void* const* d_in, const int* in_sizes, int n_in,
                              void* d_out, int out_size) {
    const float *x, *edge_attr, *lin_in_w, *lin_in_b;
    const float *msg_w1, *msg_b1, *msg_g1, *msg_be1, *msg_w2, *msg_b2, *msg_g2, *msg_be2;
    const float *upd_w1, *upd_b1, *upd_g1, *upd_be1, *upd_w2, *upd_b2, *upd_g2, *upd_be2;
    const float *pred_w, *pred_b;
    const int *edge_idx, *batch;

    if (in_sizes[1] == 2 * Ee) {
        x        = (const float*)d_in[0];
        edge_idx = (const int*)  d_in[1];
        edge_attr= (const float*)d_in[2];
        batch    = (const int*)  d_in[3];
        lin_in_w = (const float*)d_in[4];
        lin_in_b = (const float*)d_in[5];
        msg_w1   = (const float*)d_in[6];
        msg_b1   = (const float*)d_in[7];
        msg_g1   = (const float*)d_in[8];
        msg_be1  = (const float*)d_in[9];
        msg_w2   = (const float*)d_in[10];
        msg_b2   = (const float*)d_in[11];
        msg_g2   = (const float*)d_in[12];
        msg_be2  = (const float*)d_in[13];
        upd_w1   = (const float*)d_in[14];
        upd_b1   = (const float*)d_in[15];
        upd_g1   = (const float*)d_in[16];
        upd_be1  = (const float*)d_in[17];
        upd_w2   = (const float*)d_in[18];
        upd_b2   = (const float*)d_in[19];
        upd_g2   = (const float*)d_in[20];
        upd_be2  = (const float*)d_in[21];
        pred_w   = (const float*)d_in[22];
        pred_b   = (const float*)d_in[23];
    } else {
        x        = (const float*)d_in[0];
        edge_attr= (const float*)d_in[1];
        lin_in_w = (const float*)d_in[2];
        lin_in_b = (const float*)d_in[3];
        msg_w1   = (const float*)d_in[4];
        msg_b1   = (const float*)d_in[5];
        msg_g1   = (const float*)d_in[6];
        msg_be1  = (const float*)d_in[7];
        msg_w2   = (const float*)d_in[8];
        msg_b2   = (const float*)d_in[9];
        msg_g2   = (const float*)d_in[10];
        msg_be2  = (const float*)d_in[11];
        upd_w1   = (const float*)d_in[12];
        upd_b1   = (const float*)d_in[13];
        upd_g1   = (const float*)d_in[14];
        upd_be1  = (const float*)d_in[15];
        upd_w2   = (const float*)d_in[16];
        upd_b2   = (const float*)d_in[17];
        upd_g2   = (const float*)d_in[18];
        upd_be2  = (const float*)d_in[19];
        pred_w   = (const float*)d_in[20];
        pred_b   = (const float*)d_in[21];
        edge_idx = (const int*)  d_in[22];
        batch    = (const int*)  d_in[23];
    }
    float* out = (float*)d_out;

    // exact-wave grids for the big edge kernels (host-side query; capture-safe)
    int b1 = 8, b2 = 8;
    cudaOccupancyMaxActiveBlocksPerMultiprocessor(&b1, k_e1, 256, 0);
    cudaOccupancyMaxActiveBlocksPerMultiprocessor(&b2, k_e2, 256, 0);
    int grid_e1 = b1 * NSM, grid_e2 = b2 * NSM;

    // Launch order keeps k_e2 at capture slot (4th launch).
    k_zero_once<<<NBLK_SCAN, 256>>>();
    k_linpq<<<Nn / 8, dim3(32, 8)>>>(x, lin_in_w, lin_in_b, msg_w1, msg_b1);
    {
        const float* w1 = msg_w1;
        k_e1<<<grid_e1, 256>>>(edge_idx, edge_attr, w1 + 2 * EMB * EMB, 0);
        k_e2<<<grid_e2, 256>>>(msg_w2, msg_b2, msg_g1, msg_be1, 0);
    }
    // CSR build (needed only by e3u1)
    k_hist<<<(Ee + 255) / 256, 256>>>(edge_idx);
    k_scan1<<<NBLK_SCAN, 256>>>();
    k_scan2<<<1, 256>>>();
    k_scan3<<<NBLK_SCAN, 256>>>();
    k_fill<<<(Ee + 255) / 256, 256>>>(edge_idx);

    for (int l = 0; l < NL; l++) {
        const float* w1 = msg_w1 + l * (2 * EMB + ED) * EMB;
        if (l > 0) {
            k_u3pq<<<Nn / 8, dim3(32, 8)>>>(w1, msg_b1 + l * EMB,
                                            upd_g2 + (l - 1) * EMB, upd_be2 + (l - 1) * EMB,
                                            l - 1);
            k_e1<<<grid_e1, 256>>>(edge_idx, edge_attr, w1 + 2 * EMB * EMB, l);
            k_e2<<<grid_e2, 256>>>(msg_w2 + l * EMB * EMB, msg_b2 + l * EMB,
                                   msg_g1 + l * EMB, msg_be1 + l * EMB, l);
        }
        k_e3u1<<<(Nn / 4 + 7) / 8, 256>>>(upd_w1 + l * 2 * EMB * EMB, upd_b1 + l * EMB,
                                          msg_g2 + l * EMB, msg_be2 + l * EMB, l);
        k_u2<<<1184, 256>>>(upd_w2 + l * EMB * EMB, upd_b2 + l * EMB,
                            upd_g1 + l * EMB, upd_be1 + l * EMB, l);
    }
    k_u3pool<<<(Nn * 8 + 255) / 256, 256>>>(batch, upd_g2 + (NL - 1) * EMB,
                                            upd_be2 + (NL - 1) * EMB, NL - 1);
    k_pred<<<1, NB * NOUT>>>(pred_w, pred_b, out);
}

// round 12
// speedup vs baseline: 1.3461x; 1.0337x over previous
#include <cuda_runtime.h>
#include <cuda_fp16.h>

#define Nn    50000
#define Ee    800000
#define INDIM 128
#define EMB   32
#define ED    8
#define NL    4
#define NB    64
#define NOUT  10
#define EPS_BN 1e-5f
#define NBLK_SCAN 196   // ceil(Nn/256)
#define NSM   148

// ---------------- scratch (device globals) ----------------------------------
__device__ __align__(16) float  g_h[Nn * EMB];
__device__ __align__(16) float  g_p[Nn * EMB];
__device__ __align__(16) float  g_q[Nn * EMB];
__device__ __align__(16) float  g_y3[Nn * EMB];
__device__ __align__(16) float  g_y4[Nn * EMB];
__device__ __align__(16) __half g_yh[(size_t)Ee * EMB];   // y1/y2, fp16, original edge order
__device__ __align__(16) float  g_stats[NL * 4 * 2 * EMB];
__device__ __align__(16) float  g_pool[NB * EMB];
__device__ __align__(16) float  g_cnt[NB];
// CSR (built once per launch; dst is launch-invariant)
__device__ int g_deg[Nn];
__device__ int g_rowstart[Nn + 1];
__device__ int g_cursor[Nn];
__device__ int g_elist[Ee];
__device__ int g_bsum[NBLK_SCAN];
__device__ int g_boff[NBLK_SCAN];

#define STAT_IDX(l, stage, which, c) ((((l) * 4 + (stage)) * 2 + (which)) * EMB + (c))

// ---------------- helpers ---------------------------------------------------
__device__ __forceinline__ float4 f4add(float4 a, float4 b) {
    return make_float4(a.x + b.x, a.y + b.y, a.z + b.z, a.w + b.w);
}
__device__ __forceinline__ void f4fma(float4& a, float s, float4 w) {
    a.x = fmaf(s, w.x, a.x); a.y = fmaf(s, w.y, a.y);
    a.z = fmaf(s, w.z, a.z); a.w = fmaf(s, w.w, a.w);
}
__device__ __forceinline__ void store_h4(__half* p, float4 v) {
    union { __half2 h[2]; uint2 u; } cv;
    cv.h[0] = __float22half2_rn(make_float2(v.x, v.y));
    cv.h[1] = __float22half2_rn(make_float2(v.z, v.w));
    *(uint2*)p = cv.u;
}
__device__ __forceinline__ float4 load_h4(const __half* p) {
    union { uint2 u; __half2 h[2]; } cv;
    cv.u = *(const uint2*)p;
    float2 a = __half22float2(cv.h[0]);
    float2 b = __half22float2(cv.h[1]);
    return make_float4(a.x, a.y, b.x, b.y);
}

__device__ __forceinline__ void stats_warp_to_shared(float4 sum, float4 ss, int lane,
                                                     int c0, float* s_sum, float* s_ss) {
#pragma unroll
    for (int off = 8; off < 32; off <<= 1) {
        sum.x += __shfl_xor_sync(0xffffffffu, sum.x, off);
        sum.y += __shfl_xor_sync(0xffffffffu, sum.y, off);
        sum.z += __shfl_xor_sync(0xffffffffu, sum.z, off);
        sum.w += __shfl_xor_sync(0xffffffffu, sum.w, off);
        ss.x  += __shfl_xor_sync(0xffffffffu, ss.x, off);
        ss.y  += __shfl_xor_sync(0xffffffffu, ss.y, off);
        ss.z  += __shfl_xor_sync(0xffffffffu, ss.z, off);
        ss.w  += __shfl_xor_sync(0xffffffffu, ss.w, off);
    }
    if (lane < 8) {
        atomicAdd(&s_sum[c0 + 0], sum.x); atomicAdd(&s_sum[c0 + 1], sum.y);
        atomicAdd(&s_sum[c0 + 2], sum.z); atomicAdd(&s_sum[c0 + 3], sum.w);
        atomicAdd(&s_ss[c0 + 0], ss.x);   atomicAdd(&s_ss[c0 + 1], ss.y);
        atomicAdd(&s_ss[c0 + 2], ss.z);   atomicAdd(&s_ss[c0 + 3], ss.w);
    }
}

__device__ __forceinline__ void bn_coeffs(int l, int stage, float inv_n,
                                          const float* __restrict__ gamma,
                                          const float* __restrict__ beta,
                                          int c0, float sc[4], float sh[4]) {
#pragma unroll
    for (int i = 0; i < 4; i++) {
        int c = c0 + i;
        float s1 = g_stats[STAT_IDX(l, stage, 0, c)];
        float s2 = g_stats[STAT_IDX(l, stage, 1, c)];
        float mu = s1 * inv_n;
        float var = s2 * inv_n - mu * mu;
        float rs = rsqrtf(var + EPS_BN);
        sc[i] = rs * gamma[c];
        sh[i] = beta[c] - mu * sc[i];
    }
}

// ---------------- init + CSR build ------------------------------------------
__global__ void k_zero_once() {
    int i = blockIdx.x * blockDim.x + threadIdx.x;
    if (i < NL * 4 * 2 * EMB) g_stats[i] = 0.f;
    if (i < NB * EMB) g_pool[i] = 0.f;
    if (i < NB) g_cnt[i] = 0.f;
    if (i < Nn) g_deg[i] = 0;
}
__global__ void k_hist(const int* __restrict__ ei) {
    int i = blockIdx.x * blockDim.x + threadIdx.x;
    if (i < Ee) atomicAdd(&g_deg[ei[Ee + i]], 1);
}
__global__ void k_scan1() {
    __shared__ int s[256];
    int t = threadIdx.x;
    int i = blockIdx.x * 256 + t;
    int v = (i < Nn) ? g_deg[i] : 0;
    s[t] = v;
    __syncthreads();
#pragma unroll
    for (int off = 1; off < 256; off <<= 1) {
        int add = (t >= off) ? s[t - off] : 0;
        __syncthreads();
        s[t] += add;
        __syncthreads();
    }
    if (i < Nn) g_rowstart[i + 1] = s[t];
    if (t == 255) g_bsum[blockIdx.x] = s[255];
}
__global__ void k_scan2() {
    __shared__ int s[256];
    int t = threadIdx.x;
    int v = (t < NBLK_SCAN) ? g_bsum[t] : 0;
    s[t] = v;
    __syncthreads();
#pragma unroll
    for (int off = 1; off < 256; off <<= 1) {
        int add = (t >= off) ? s[t - off] : 0;
        __syncthreads();
        s[t] += add;
        __syncthreads();
    }
    if (t < NBLK_SCAN) g_boff[t] = s[t] - v;   // exclusive
}
__global__ void k_scan3() {
    int i = blockIdx.x * blockDim.x + threadIdx.x;
    if (i < Nn) {
        int v = g_rowstart[i + 1] + g_boff[i >> 8];
        g_rowstart[i + 1] = v;
        g_cursor[i] = v - g_deg[i];
    }
    if (i == 0) g_rowstart[0] = 0;
}
__global__ void k_fill(const int* __restrict__ ei) {
    int i = blockIdx.x * blockDim.x + threadIdx.x;
    if (i < Ee) {
        int d = ei[Ee + i];
        int pos = atomicAdd(&g_cursor[d], 1);
        g_elist[pos] = i;
    }
}

// ---- fused lin_in + pq(layer0) ----------------------------------------------
__global__ void k_linpq(const float* __restrict__ x, const float* __restrict__ w,
                        const float* __restrict__ b,
                        const float* __restrict__ w1, const float* __restrict__ b1) {
    __shared__ float ws[INDIM * EMB];
    __shared__ float xs[8][INDIM];
    __shared__ float wd[EMB * EMB];
    __shared__ float wsr[EMB * EMB];
    __shared__ float hs[8][EMB];
    int tx = threadIdx.x, ty = threadIdx.y;
    int tid = ty * 32 + tx;
    for (int i = tid; i < INDIM * EMB; i += 256) ws[i] = w[i];
    for (int i = tid; i < EMB * EMB; i += 256) { wd[i] = w1[i]; wsr[i] = w1[EMB * EMB + i]; }
    int base = blockIdx.x * 8;
    for (int i = tid; i < 8 * INDIM; i += 256) {
        int nloc = i >> 7, k = i & 127;
        xs[nloc][k] = x[(base + nloc) * INDIM + k];
    }
    __syncthreads();
    float acc = b[tx];
#pragma unroll 8
    for (int k = 0; k < INDIM; k++) acc = fmaf(xs[ty][k], ws[k * EMB + tx], acc);
    int n = base + ty;
    g_h[n * EMB + tx] = acc;
    hs[ty][tx] = acc;
    __syncthreads();
    float ap = b1[tx], aq = 0.f;
#pragma unroll
    for (int k = 0; k < EMB; k++) {
        float hv = hs[ty][k];
        ap = fmaf(hv, wd[k * EMB + tx], ap);
        aq = fmaf(hv, wsr[k * EMB + tx], aq);
    }
    g_p[n * EMB + tx] = ap;
    g_q[n * EMB + tx] = aq;
}

// ---- fused u3(prev layer) + pq(this layer) ---------------------------------
__global__ void k_u3pq(const float* __restrict__ w1, const float* __restrict__ b1,
                       const float* __restrict__ g2, const float* __restrict__ be2,
                       int prev) {
    __shared__ float wd[EMB * EMB];
    __shared__ float wsr[EMB * EMB];
    __shared__ float hs[8][EMB];
    int tx = threadIdx.x, ty = threadIdx.y;
    int tid = ty * 32 + tx;
    for (int i = tid; i < EMB * EMB; i += 256) { wd[i] = w1[i]; wsr[i] = w1[EMB * EMB + i]; }
    float s1 = g_stats[STAT_IDX(prev, 3, 0, tx)];
    float s2 = g_stats[STAT_IDX(prev, 3, 1, tx)];
    float mu = s1 * (1.f / Nn);
    float var = s2 * (1.f / Nn) - mu * mu;
    float rs = rsqrtf(var + EPS_BN);
    float sc = rs * g2[tx];
    float sh = be2[tx] - mu * sc;
    int base = blockIdx.x * 8;
    int n = base + ty;
    float hv = g_h[n * EMB + tx] + fmaxf(fmaf(g_y4[n * EMB + tx], sc, sh), 0.f);
    g_h[n * EMB + tx] = hv;
    hs[ty][tx] = hv;
    __syncthreads();
    float ap = b1[tx], aq = 0.f;
#pragma unroll
    for (int k = 0; k < EMB; k++) {
        float h2 = hs[ty][k];
        ap = fmaf(h2, wd[k * EMB + tx], ap);
        aq = fmaf(h2, wsr[k * EMB + tx], aq);
    }
    g_p[n * EMB + tx] = ap;
    g_q[n * EMB + tx] = aq;
}

// ---- E1 (register-blocked, 4 quads per weight pass) ------------------------
// y1 = p[dst]+q[src]+ea@Wc -> g_yh ; stats stage 0.
__global__ void __launch_bounds__(256) k_e1(const int* __restrict__ ei,
                     const float* __restrict__ ea,
                     const float* __restrict__ wc, int layer) {
    __shared__ float4 s_w[64];      // [k][cg]
    __shared__ float s_sum[EMB], s_ss[EMB];
    int tid = threadIdx.x;
    if (tid < 64) s_w[tid] = *(const float4*)(wc + (tid >> 3) * EMB + (tid & 7) * 4);
    if (tid < EMB) { s_sum[tid] = 0.f; s_ss[tid] = 0.f; }
    __syncthreads();
    int lane = tid & 31;
    int es = lane >> 3, cg = lane & 7, c0 = cg * 4;
    int nw = gridDim.x * (blockDim.x >> 5);
    int gw = blockIdx.x * (blockDim.x >> 5) + (tid >> 5);
    float4 sum = make_float4(0, 0, 0, 0), ss = make_float4(0, 0, 0, 0);
    const int NQ = Ee / 4;   // 200000, divisible by 4
    for (int q0 = gw * 4; q0 < NQ; q0 += nw * 4) {
        // phase 1: batch index loads + gathers + ea loads (MLP up to 8+)
        float4 y[4], ea0[4], ea1[4];
#pragma unroll
        for (int k = 0; k < 4; k++) {
            int e = (q0 + k) * 4 + es;
            int s = ei[e], d = ei[Ee + e];
            float4 pv = *(const float4*)(g_p + d * EMB + c0);
            float4 qv = *(const float4*)(g_q + s * EMB + c0);
            y[k] = f4add(pv, qv);
            const float4* eap = (const float4*)(ea + (size_t)e * ED);
            ea0[k] = eap[0];
            ea1[k] = eap[1];
        }
        // phase 2: one weight pass serves 4 quads (16 edges)
#pragma unroll
        for (int kk = 0; kk < 8; kk++) {
            float4 wv = s_w[kk * 8 + cg];
#pragma unroll
            for (int k = 0; k < 4; k++) {
                float evk;
                switch (kk) {
                    case 0: evk = ea0[k].x; break;
                    case 1: evk = ea0[k].y; break;
                    case 2: evk = ea0[k].z; break;
                    case 3: evk = ea0[k].w; break;
                    case 4: evk = ea1[k].x; break;
                    case 5: evk = ea1[k].y; break;
                    case 6: evk = ea1[k].z; break;
                    default: evk = ea1[k].w; break;
                }
                f4fma(y[k], evk, wv);
            }
        }
#pragma unroll
        for (int k = 0; k < 4; k++) {
            int e = (q0 + k) * 4 + es;
            store_h4(g_yh + (size_t)e * EMB + c0, y[k]);
            sum = f4add(sum, y[k]);
            ss.x = fmaf(y[k].x, y[k].x, ss.x);
            ss.y = fmaf(y[k].y, y[k].y, ss.y);
            ss.z = fmaf(y[k].z, y[k].z, ss.z);
            ss.w = fmaf(y[k].w, y[k].w, ss.w);
        }
    }
    stats_warp_to_shared(sum, ss, lane, c0, s_sum, s_ss);
    __syncthreads();
    if (tid < EMB) {
        atomicAdd(&g_stats[STAT_IDX(layer, 0, 0, tid)], s_sum[tid]);
        atomicAdd(&g_stats[STAT_IDX(layer, 0, 1, tid)], s_ss[tid]);
    }
}

// ---- E2 (register-blocked): each lane carries 4 quads per W2 fetch ---------
__global__ void __launch_bounds__(256) k_e2(const float* __restrict__ w2,
                     const float* __restrict__ b2,
                     const float* __restrict__ g1, const float* __restrict__ be1, int layer) {
    __shared__ float s_w2[EMB * EMB];
    __shared__ float s_sum[EMB], s_ss[EMB];
    int tid = threadIdx.x;
    for (int i = tid; i < EMB * EMB; i += 256) s_w2[i] = w2[i];
    if (tid < EMB) { s_sum[tid] = 0.f; s_ss[tid] = 0.f; }
    __syncthreads();
    int lane = tid & 31;
    int es = lane >> 3, cg = lane & 7, c0 = cg * 4, base = lane & 24;
    float sc[4], sh[4];
    bn_coeffs(layer, 0, 1.f / Ee, g1, be1, c0, sc, sh);
    float4 bb = *(const float4*)(b2 + c0);
    const float4* w2v = (const float4*)s_w2;
    int nw = gridDim.x * (blockDim.x >> 5);
    int gw = blockIdx.x * (blockDim.x >> 5) + (tid >> 5);
    float4 sum = make_float4(0, 0, 0, 0), ssq = make_float4(0, 0, 0, 0);
    const int NQ = Ee / 4;
    for (int q0 = gw * 4; q0 < NQ; q0 += nw * 4) {
        float m[4][4];
        float4 acc[4];
#pragma unroll
        for (int k = 0; k < 4; k++) {
            int e = (q0 + k) * 4 + es;
            float4 y1 = load_h4(g_yh + (size_t)e * EMB + c0);
            m[k][0] = fmaxf(fmaf(y1.x, sc[0], sh[0]), 0.f);
            m[k][1] = fmaxf(fmaf(y1.y, sc[1], sh[1]), 0.f);
            m[k][2] = fmaxf(fmaf(y1.z, sc[2], sh[2]), 0.f);
            m[k][3] = fmaxf(fmaf(y1.w, sc[3], sh[3]), 0.f);
            acc[k] = bb;
        }
#pragma unroll
        for (int j = 0; j < EMB; j++) {
            float4 wv = w2v[j * 8 + cg];
#pragma unroll
            for (int k = 0; k < 4; k++) {
                float mj = __shfl_sync(0xffffffffu, m[k][j & 3], base + (j >> 2));
                f4fma(acc[k], mj, wv);
            }
        }
#pragma unroll
        for (int k = 0; k < 4; k++) {
            int e = (q0 + k) * 4 + es;
            store_h4(g_yh + (size_t)e * EMB + c0, acc[k]);
            sum = f4add(sum, acc[k]);
            ssq.x = fmaf(acc[k].x, acc[k].x, ssq.x);
            ssq.y = fmaf(acc[k].y, acc[k].y, ssq.y);
            ssq.z = fmaf(acc[k].z, acc[k].z, ssq.z);
            ssq.w = fmaf(acc[k].w, acc[k].w, ssq.w);
        }
    }
    stats_warp_to_shared(sum, ssq, lane, c0, s_sum, s_ss);
    __syncthreads();
    if (tid < EMB) {
        atomicAdd(&g_stats[STAT_IDX(layer, 1, 0, tid)], s_sum[tid]);
        atomicAdd(&g_stats[STAT_IDX(layer, 1, 1, tid)], s_ss[tid]);
    }
}

// ---- fused E3+U1: aggr via elist gathers (prefetched); y3; stats stage 2 ---
__global__ void __launch_bounds__(256) k_e3u1(const float* __restrict__ w,
                       const float* __restrict__ b,
                       const float* __restrict__ g2, const float* __restrict__ be2,
                       int layer) {
    __shared__ float sw[2 * EMB * EMB];
    __shared__ float s_sum[EMB], s_ss[EMB];
    int tid = threadIdx.x;
    for (int i = tid; i < 2 * EMB * EMB; i += 256) sw[i] = w[i];
    if (tid < EMB) { s_sum[tid] = 0.f; s_ss[tid] = 0.f; }
    __syncthreads();
    int lane = tid & 31;
    int es = lane >> 3, cg = lane & 7, c0 = cg * 4, base = lane & 24;
    float4 sum = make_float4(0, 0, 0, 0), ssq = make_float4(0, 0, 0, 0);

    int quad = blockIdx.x * 8 + (tid >> 5);
    if (quad * 4 < Nn) {
        float sc[4], sh[4];
        bn_coeffs(layer, 1, 1.f / Ee, g2, be2, c0, sc, sh);
        int n = quad * 4 + es;
        int rs = g_rowstart[n], re = g_rowstart[n + 1];
        float4 ag = make_float4(0, 0, 0, 0);
        int e_nxt = (rs < re) ? g_elist[rs] : 0;
        for (int i = rs; i < re; i++) {
            int e = e_nxt;
            if (i + 1 < re) e_nxt = g_elist[i + 1];
            float4 y = load_h4(g_yh + (size_t)e * EMB + c0);
            ag.x += fmaxf(fmaf(y.x, sc[0], sh[0]), 0.f);
            ag.y += fmaxf(fmaf(y.y, sc[1], sh[1]), 0.f);
            ag.z += fmaxf(fmaf(y.z, sc[2], sh[2]), 0.f);
            ag.w += fmaxf(fmaf(y.w, sc[3], sh[3]), 0.f);
        }
        float4 h4 = *(const float4*)(g_h + n * EMB + c0);
        float hr[4] = {h4.x, h4.y, h4.z, h4.w};
        float ar[4] = {ag.x, ag.y, ag.z, ag.w};
        const float4* swv = (const float4*)sw;
        float4 acc = *(const float4*)(b + c0);
#pragma unroll
        for (int j = 0; j < EMB; j++) {
            float hj = __shfl_sync(0xffffffffu, hr[j & 3], base + (j >> 2));
            f4fma(acc, hj, swv[j * 8 + cg]);
        }
#pragma unroll
        for (int j = 0; j < EMB; j++) {
            float aj = __shfl_sync(0xffffffffu, ar[j & 3], base + (j >> 2));
            f4fma(acc, aj, swv[(EMB + j) * 8 + cg]);
        }
        *(float4*)(g_y3 + n * EMB + c0) = acc;
        sum = acc;
        ssq.x = acc.x * acc.x; ssq.y = acc.y * acc.y;
        ssq.z = acc.z * acc.z; ssq.w = acc.w * acc.w;
    }
    stats_warp_to_shared(sum, ssq, lane, c0, s_sum, s_ss);
    __syncthreads();
    if (tid < EMB) {
        atomicAdd(&g_stats[STAT_IDX(layer, 2, 0, tid)], s_sum[tid]);
        atomicAdd(&g_stats[STAT_IDX(layer, 2, 1, tid)], s_ss[tid]);
    }
}

// ---------------- U2: r = relu(bn(y3)) ; y4 = r@Wu2+b ; stats stage 3 -------
__global__ void k_u2(const float* __restrict__ w2, const float* __restrict__ b2,
                     const float* __restrict__ g1, const float* __restrict__ be1, int layer) {
    __shared__ float s_w2[EMB * EMB];
    __shared__ float s_sum[EMB], s_ss[EMB];
    int tid = threadIdx.x;
    for (int i = tid; i < EMB * EMB; i += 256) s_w2[i] = w2[i];
    if (tid < EMB) { s_sum[tid] = 0.f; s_ss[tid] = 0.f; }
    __syncthreads();
    int lane = tid & 31;
    int es = lane >> 3, cg = lane & 7, c0 = cg * 4, base = lane & 24;
    float sc[4], sh[4];
    bn_coeffs(layer, 2, 1.f / Nn, g1, be1, c0, sc, sh);
    float4 bb = *(const float4*)(b2 + c0);
    const float4* w2v = (const float4*)s_w2;
    int nw = gridDim.x * (blockDim.x >> 5);
    int gw = blockIdx.x * (blockDim.x >> 5) + (tid >> 5);
    float4 sum = make_float4(0, 0, 0, 0), ssq = make_float4(0, 0, 0, 0);
    for (int qd = gw; qd < Nn / 4; qd += nw) {
        int n = qd * 4 + es;
        float4 y1 = *(const float4*)(g_y3 + n * EMB + c0);
        float m[4];
        m[0] = fmaxf(fmaf(y1.x, sc[0], sh[0]), 0.f);
        m[1] = fmaxf(fmaf(y1.y, sc[1], sh[1]), 0.f);
        m[2] = fmaxf(fmaf(y1.z, sc[2], sh[2]), 0.f);
        m[3] = fmaxf(fmaf(y1.w, sc[3], sh[3]), 0.f);
        float4 acc = bb;
#pragma unroll
        for (int j = 0; j < EMB; j++) {
            float mj = __shfl_sync(0xffffffffu, m[j & 3], base + (j >> 2));
            f4fma(acc, mj, w2v[j * 8 + cg]);
        }
        *(float4*)(g_y4 + n * EMB + c0) = acc;
        sum = f4add(sum, acc);
        ssq.x = fmaf(acc.x, acc.x, ssq.x); ssq.y = fmaf(acc.y, acc.y, ssq.y);
        ssq.z = fmaf(acc.z, acc.z, ssq.z); ssq.w = fmaf(acc.w, acc.w, ssq.w);
    }
    stats_warp_to_shared(sum, ssq, lane, c0, s_sum, s_ss);
    __syncthreads();
    if (tid < EMB) {
        atomicAdd(&g_stats[STAT_IDX(layer, 3, 0, tid)], s_sum[tid]);
        atomicAdd(&g_stats[STAT_IDX(layer, 3, 1, tid)], s_ss[tid]);
    }
}

// ---- final layer: h_final = h + relu(bn(y4)); pool atomics -----------------
__global__ void k_u3pool(const int* __restrict__ batch,
                         const float* __restrict__ g2, const float* __restrict__ be2,
                         int layer) {
    int idx = blockIdx.x * blockDim.x + threadIdx.x;
    if (idx >= Nn * 8) return;
    int n = idx >> 3, cg = idx & 7, c0 = cg * 4;
    float sc[4], sh[4];
    bn_coeffs(layer, 3, 1.f / Nn, g2, be2, c0, sc, sh);
    float4 y = *(const float4*)(g_y4 + n * EMB + c0);
    float4 h = *(const float4*)(g_h + n * EMB + c0);
    h.x += fmaxf(fmaf(y.x, sc[0], sh[0]), 0.f);
    h.y += fmaxf(fmaf(y.y, sc[1], sh[1]), 0.f);
    h.z += fmaxf(fmaf(y.z, sc[2], sh[2]), 0.f);
    h.w += fmaxf(fmaf(y.w, sc[3], sh[3]), 0.f);
    int b = batch[n];
    float* pp = g_pool + b * EMB + c0;
    atomicAdd(pp + 0, h.x); atomicAdd(pp + 1, h.y);
    atomicAdd(pp + 2, h.z); atomicAdd(pp + 3, h.w);
    if (cg == 0) atomicAdd(&g_cnt[b], 1.0f);
}

__global__ void k_pred(const float* __restrict__ pw, const float* __restrict__ pb,
                       float* __restrict__ out) {
    int t = threadIdx.x;
    if (t >= NB * NOUT) return;
    int b = t / NOUT, o = t % NOUT;
    float inv = 1.f / fmaxf(g_cnt[b], 1.f);
    float s = 0.f;
#pragma unroll
    for (int j = 0; j < EMB; j++) s = fmaf(g_pool[b * EMB + j], pw[j * NOUT + o], s);
    out[t] = pb[o] + s * inv;
}

// ---------------- launch -----------------------------------------------------
extern "C" void kernel_launch(void* const* d_in, const int* in_sizes, int n_in,
                              void* d_out, int out_size) {
    const float *x, *edge_attr, *lin_in_w, *lin_in_b;
    const float *msg_w1, *msg_b1, *msg_g1, *msg_be1, *msg_w2, *msg_b2, *msg_g2, *msg_be2;
    const float *upd_w1, *upd_b1, *upd_g1, *upd_be1, *upd_w2, *upd_b2, *upd_g2, *upd_be2;
    const float *pred_w, *pred_b;
    const int *edge_idx, *batch;

    if (in_sizes[1] == 2 * Ee) {
        x        = (const float*)d_in[0];
        edge_idx = (const int*)  d_in[1];
        edge_attr= (const float*)d_in[2];
        batch    = (const int*)  d_in[3];
        lin_in_w = (const float*)d_in[4];
        lin_in_b = (const float*)d_in[5];
        msg_w1   = (const float*)d_in[6];
        msg_b1   = (const float*)d_in[7];
        msg_g1   = (const float*)d_in[8];
        msg_be1  = (const float*)d_in[9];
        msg_w2   = (const float*)d_in[10];
        msg_b2   = (const float*)d_in[11];
        msg_g2   = (const float*)d_in[12];
        msg_be2  = (const float*)d_in[13];
        upd_w1   = (const float*)d_in[14];
        upd_b1   = (const float*)d_in[15];
        upd_g1   = (const float*)d_in[16];
        upd_be1  = (const float*)d_in[17];
        upd_w2   = (const float*)d_in[18];
        upd_b2   = (const float*)d_in[19];
        upd_g2   = (const float*)d_in[20];
        upd_be2  = (const float*)d_in[21];
        pred_w   = (const float*)d_in[22];
        pred_b   = (const float*)d_in[23];
    } else {
        x        = (const float*)d_in[0];
        edge_attr= (const float*)d_in[1];
        lin_in_w = (const float*)d_in[2];
        lin_in_b = (const float*)d_in[3];
        msg_w1   = (const float*)d_in[4];
        msg_b1   = (const float*)d_in[5];
        msg_g1   = (const float*)d_in[6];
        msg_be1  = (const float*)d_in[7];
        msg_w2   = (const float*)d_in[8];
        msg_b2   = (const float*)d_in[9];
        msg_g2   = (const float*)d_in[10];
        msg_be2  = (const float*)d_in[11];
        upd_w1   = (const float*)d_in[12];
        upd_b1   = (const float*)d_in[13];
        upd_g1   = (const float*)d_in[14];
        upd_be1  = (const float*)d_in[15];
        upd_w2   = (const float*)d_in[16];
        upd_b2   = (const float*)d_in[17];
        upd_g2   = (const float*)d_in[18];
        upd_be2  = (const float*)d_in[19];
        pred_w   = (const float*)d_in[20];
        pred_b   = (const float*)d_in[21];
        edge_idx = (const int*)  d_in[22];
        batch    = (const int*)  d_in[23];
    }
    float* out = (float*)d_out;

    // exact-wave grids for the big edge kernels (host-side query; capture-safe)
    int b1 = 4, b2 = 2;
    cudaOccupancyMaxActiveBlocksPerMultiprocessor(&b1, k_e1, 256, 0);
    cudaOccupancyMaxActiveBlocksPerMultiprocessor(&b2, k_e2, 256, 0);
    int grid_e1 = b1 * NSM, grid_e2 = b2 * NSM;

    // Launch order puts k_e1 at capture slot (4th launch):
    // 0: zero, 1: linpq, 2: hist (independent), 3: e1(l0), 4: e2(l0), CSR rest...
    k_zero_once<<<NBLK_SCAN, 256>>>();
    k_linpq<<<Nn / 8, dim3(32, 8)>>>(x, lin_in_w, lin_in_b, msg_w1, msg_b1);
    k_hist<<<(Ee + 255) / 256, 256>>>(edge_idx);
    {
        const float* w1 = msg_w1;
        k_e1<<<grid_e1, 256>>>(edge_idx, edge_attr, w1 + 2 * EMB * EMB, 0);
        k_e2<<<grid_e2, 256>>>(msg_w2, msg_b2, msg_g1, msg_be1, 0);
    }
    // CSR build (needed only by e3u1)
    k_scan1<<<NBLK_SCAN, 256>>>();
    k_scan2<<<1, 256>>>();
    k_scan3<<<NBLK_SCAN, 256>>>();
    k_fill<<<(Ee + 255) / 256, 256>>>(edge_idx);

    for (int l = 0; l < NL; l++) {
        const float* w1 = msg_w1 + l * (2 * EMB + ED) * EMB;
        if (l > 0) {
            k_u3pq<<<Nn / 8, dim3(32, 8)>>>(w1, msg_b1 + l * EMB,
                                            upd_g2 + (l - 1) * EMB, upd_be2 + (l - 1) * EMB,
                                            l - 1);
            k_e1<<<grid_e1, 256>>>(edge_idx, edge_attr, w1 + 2 * EMB * EMB, l);
            k_e2<<<grid_e2, 256>>>(msg_w2 + l * EMB * EMB, msg_b2 + l * EMB,
                                   msg_g1 + l * EMB, msg_be1 + l * EMB, l);
        }
        k_e3u1<<<(Nn / 4 + 7) / 8, 256>>>(upd_w1 + l * 2 * EMB * EMB, upd_b1 + l * EMB,
                                          msg_g2 + l * EMB, msg_be2 + l * EMB, l);
        k_u2<<<1184, 256>>>(upd_w2 + l * EMB * EMB, upd_b2 + l * EMB,
                            upd_g1 + l * EMB, upd_be1 + l * EMB, l);
    }
    k_u3pool<<<(Nn * 8 + 255) / 256, 256>>>(batch, upd_g2 + (NL - 1) * EMB,
                                            upd_be2 + (NL - 1) * EMB, NL - 1);
    k_pred<<<1, NB * NOUT>>>(pred_w, pred_b, out);
}

// round 13
// speedup vs baseline: 1.3639x; 1.0133x over previous
#include <cuda_runtime.h>
#include <cuda_fp16.h>

#define Nn    50000
#define Ee    800000
#define INDIM 128
#define EMB   32
#define ED    8
#define NL    4
#define NB    64
#define NOUT  10
#define EPS_BN 1e-5f
#define NBLK_SCAN 196   // ceil(Nn/256)
#define NSM   148

// ---------------- scratch (device globals) ----------------------------------
__device__ __align__(16) float  g_h[Nn * EMB];
__device__ __align__(16) float  g_p[Nn * EMB];
__device__ __align__(16) float  g_q[Nn * EMB];
__device__ __align__(16) float  g_y3[Nn * EMB];
__device__ __align__(16) float  g_y4[Nn * EMB];
__device__ __align__(16) __half g_yh[(size_t)Ee * EMB];   // y1, fp16, edge order
__device__ __align__(16) __half g_yh2[(size_t)Ee * EMB];  // y2, fp16, CSR order
__device__ __align__(16) float  g_stats[NL * 4 * 2 * EMB];
__device__ __align__(16) float  g_pool[NB * EMB];
__device__ __align__(16) float  g_cnt[NB];
// CSR (built once per launch; dst is launch-invariant)
__device__ int g_deg[Nn];
__device__ int g_rowstart[Nn + 1];
__device__ int g_cursor[Nn];
__device__ int g_pos[Ee];        // edge -> CSR slot
__device__ int g_bsum[NBLK_SCAN];
__device__ int g_boff[NBLK_SCAN];

#define STAT_IDX(l, stage, which, c) ((((l) * 4 + (stage)) * 2 + (which)) * EMB + (c))

// ---------------- helpers ---------------------------------------------------
__device__ __forceinline__ float4 f4add(float4 a, float4 b) {
    return make_float4(a.x + b.x, a.y + b.y, a.z + b.z, a.w + b.w);
}
__device__ __forceinline__ void f4fma(float4& a, float s, float4 w) {
    a.x = fmaf(s, w.x, a.x); a.y = fmaf(s, w.y, a.y);
    a.z = fmaf(s, w.z, a.z); a.w = fmaf(s, w.w, a.w);
}
__device__ __forceinline__ void store_h4(__half* p, float4 v) {
    union { __half2 h[2]; uint2 u; } cv;
    cv.h[0] = __float22half2_rn(make_float2(v.x, v.y));
    cv.h[1] = __float22half2_rn(make_float2(v.z, v.w));
    *(uint2*)p = cv.u;
}
__device__ __forceinline__ float4 load_h4(const __half* p) {
    union { uint2 u; __half2 h[2]; } cv;
    cv.u = *(const uint2*)p;
    float2 a = __half22float2(cv.h[0]);
    float2 b = __half22float2(cv.h[1]);
    return make_float4(a.x, a.y, b.x, b.y);
}

__device__ __forceinline__ void stats_warp_to_shared(float4 sum, float4 ss, int lane,
                                                     int c0, float* s_sum, float* s_ss) {
#pragma unroll
    for (int off = 8; off < 32; off <<= 1) {
        sum.x += __shfl_xor_sync(0xffffffffu, sum.x, off);
        sum.y += __shfl_xor_sync(0xffffffffu, sum.y, off);
        sum.z += __shfl_xor_sync(0xffffffffu, sum.z, off);
        sum.w += __shfl_xor_sync(0xffffffffu, sum.w, off);
        ss.x  += __shfl_xor_sync(0xffffffffu, ss.x, off);
        ss.y  += __shfl_xor_sync(0xffffffffu, ss.y, off);
        ss.z  += __shfl_xor_sync(0xffffffffu, ss.z, off);
        ss.w  += __shfl_xor_sync(0xffffffffu, ss.w, off);
    }
    if (lane < 8) {
        atomicAdd(&s_sum[c0 + 0], sum.x); atomicAdd(&s_sum[c0 + 1], sum.y);
        atomicAdd(&s_sum[c0 + 2], sum.z); atomicAdd(&s_sum[c0 + 3], sum.w);
        atomicAdd(&s_ss[c0 + 0], ss.x);   atomicAdd(&s_ss[c0 + 1], ss.y);
        atomicAdd(&s_ss[c0 + 2], ss.z);   atomicAdd(&s_ss[c0 + 3], ss.w);
    }
}

__device__ __forceinline__ void bn_coeffs(int l, int stage, float inv_n,
                                          const float* __restrict__ gamma,
                                          const float* __restrict__ beta,
                                          int c0, float sc[4], float sh[4]) {
#pragma unroll
    for (int i = 0; i < 4; i++) {
        int c = c0 + i;
        float s1 = g_stats[STAT_IDX(l, stage, 0, c)];
        float s2 = g_stats[STAT_IDX(l, stage, 1, c)];
        float mu = s1 * inv_n;
        float var = s2 * inv_n - mu * mu;
        float rs = rsqrtf(var + EPS_BN);
        sc[i] = rs * gamma[c];
        sh[i] = beta[c] - mu * sc[i];
    }
}

// ---------------- init + CSR build ------------------------------------------
__global__ void k_zero_once() {
    int i = blockIdx.x * blockDim.x + threadIdx.x;
    if (i < NL * 4 * 2 * EMB) g_stats[i] = 0.f;
    if (i < NB * EMB) g_pool[i] = 0.f;
    if (i < NB) g_cnt[i] = 0.f;
    if (i < Nn) g_deg[i] = 0;
}
__global__ void k_hist(const int* __restrict__ ei) {
    int i = blockIdx.x * blockDim.x + threadIdx.x;
    if (i < Ee) atomicAdd(&g_deg[ei[Ee + i]], 1);
}
__global__ void k_scan1() {
    __shared__ int s[256];
    int t = threadIdx.x;
    int i = blockIdx.x * 256 + t;
    int v = (i < Nn) ? g_deg[i] : 0;
    s[t] = v;
    __syncthreads();
#pragma unroll
    for (int off = 1; off < 256; off <<= 1) {
        int add = (t >= off) ? s[t - off] : 0;
        __syncthreads();
        s[t] += add;
        __syncthreads();
    }
    if (i < Nn) g_rowstart[i + 1] = s[t];
    if (t == 255) g_bsum[blockIdx.x] = s[255];
}
__global__ void k_scan2() {
    __shared__ int s[256];
    int t = threadIdx.x;
    int v = (t < NBLK_SCAN) ? g_bsum[t] : 0;
    s[t] = v;
    __syncthreads();
#pragma unroll
    for (int off = 1; off < 256; off <<= 1) {
        int add = (t >= off) ? s[t - off] : 0;
        __syncthreads();
        s[t] += add;
        __syncthreads();
    }
    if (t < NBLK_SCAN) g_boff[t] = s[t] - v;   // exclusive
}
__global__ void k_scan3() {
    int i = blockIdx.x * blockDim.x + threadIdx.x;
    if (i < Nn) {
        int v = g_rowstart[i + 1] + g_boff[i >> 8];
        g_rowstart[i + 1] = v;
        g_cursor[i] = v - g_deg[i];
    }
    if (i == 0) g_rowstart[0] = 0;
}
__global__ void k_fill(const int* __restrict__ ei) {
    int i = blockIdx.x * blockDim.x + threadIdx.x;
    if (i < Ee) {
        int d = ei[Ee + i];
        g_pos[i] = atomicAdd(&g_cursor[d], 1);
    }
}

// ---- fused lin_in + pq(layer0) ----------------------------------------------
__global__ void k_linpq(const float* __restrict__ x, const float* __restrict__ w,
                        const float* __restrict__ b,
                        const float* __restrict__ w1, const float* __restrict__ b1) {
    __shared__ float ws[INDIM * EMB];
    __shared__ float xs[8][INDIM];
    __shared__ float wd[EMB * EMB];
    __shared__ float wsr[EMB * EMB];
    __shared__ float hs[8][EMB];
    int tx = threadIdx.x, ty = threadIdx.y;
    int tid = ty * 32 + tx;
    for (int i = tid; i < INDIM * EMB; i += 256) ws[i] = w[i];
    for (int i = tid; i < EMB * EMB; i += 256) { wd[i] = w1[i]; wsr[i] = w1[EMB * EMB + i]; }
    int base = blockIdx.x * 8;
    for (int i = tid; i < 8 * INDIM; i += 256) {
        int nloc = i >> 7, k = i & 127;
        xs[nloc][k] = x[(base + nloc) * INDIM + k];
    }
    __syncthreads();
    float acc = b[tx];
#pragma unroll 8
    for (int k = 0; k < INDIM; k++) acc = fmaf(xs[ty][k], ws[k * EMB + tx], acc);
    int n = base + ty;
    g_h[n * EMB + tx] = acc;
    hs[ty][tx] = acc;
    __syncthreads();
    float ap = b1[tx], aq = 0.f;
#pragma unroll
    for (int k = 0; k < EMB; k++) {
        float hv = hs[ty][k];
        ap = fmaf(hv, wd[k * EMB + tx], ap);
        aq = fmaf(hv, wsr[k * EMB + tx], aq);
    }
    g_p[n * EMB + tx] = ap;
    g_q[n * EMB + tx] = aq;
}

// ---- fused u3(prev layer) + pq(this layer) ---------------------------------
__global__ void k_u3pq(const float* __restrict__ w1, const float* __restrict__ b1,
                       const float* __restrict__ g2, const float* __restrict__ be2,
                       int prev) {
    __shared__ float wd[EMB * EMB];
    __shared__ float wsr[EMB * EMB];
    __shared__ float hs[8][EMB];
    int tx = threadIdx.x, ty = threadIdx.y;
    int tid = ty * 32 + tx;
    for (int i = tid; i < EMB * EMB; i += 256) { wd[i] = w1[i]; wsr[i] = w1[EMB * EMB + i]; }
    float s1 = g_stats[STAT_IDX(prev, 3, 0, tx)];
    float s2 = g_stats[STAT_IDX(prev, 3, 1, tx)];
    float mu = s1 * (1.f / Nn);
    float var = s2 * (1.f / Nn) - mu * mu;
    float rs = rsqrtf(var + EPS_BN);
    float sc = rs * g2[tx];
    float sh = be2[tx] - mu * sc;
    int base = blockIdx.x * 8;
    int n = base + ty;
    float hv = g_h[n * EMB + tx] + fmaxf(fmaf(g_y4[n * EMB + tx], sc, sh), 0.f);
    g_h[n * EMB + tx] = hv;
    hs[ty][tx] = hv;
    __syncthreads();
    float ap = b1[tx], aq = 0.f;
#pragma unroll
    for (int k = 0; k < EMB; k++) {
        float h2 = hs[ty][k];
        ap = fmaf(h2, wd[k * EMB + tx], ap);
        aq = fmaf(h2, wsr[k * EMB + tx], aq);
    }
    g_p[n * EMB + tx] = ap;
    g_q[n * EMB + tx] = aq;
}

// ---- E1 (register-blocked, 4 quads per weight pass) ------------------------
__global__ void __launch_bounds__(256) k_e1(const int* __restrict__ ei,
                     const float* __restrict__ ea,
                     const float* __restrict__ wc, int layer) {
    __shared__ float4 s_w[64];      // [k][cg]
    __shared__ float s_sum[EMB], s_ss[EMB];
    int tid = threadIdx.x;
    if (tid < 64) s_w[tid] = *(const float4*)(wc + (tid >> 3) * EMB + (tid & 7) * 4);
    if (tid < EMB) { s_sum[tid] = 0.f; s_ss[tid] = 0.f; }
    __syncthreads();
    int lane = tid & 31;
    int es = lane >> 3, cg = lane & 7, c0 = cg * 4;
    int nw = gridDim.x * (blockDim.x >> 5);
    int gw = blockIdx.x * (blockDim.x >> 5) + (tid >> 5);
    float4 sum = make_float4(0, 0, 0, 0), ss = make_float4(0, 0, 0, 0);
    const int NQ = Ee / 4;
    for (int q0 = gw * 4; q0 < NQ; q0 += nw * 4) {
        float4 y[4], ea0[4], ea1[4];
#pragma unroll
        for (int k = 0; k < 4; k++) {
            int e = (q0 + k) * 4 + es;
            int s = ei[e], d = ei[Ee + e];
            float4 pv = *(const float4*)(g_p + d * EMB + c0);
            float4 qv = *(const float4*)(g_q + s * EMB + c0);
            y[k] = f4add(pv, qv);
            const float4* eap = (const float4*)(ea + (size_t)e * ED);
            ea0[k] = eap[0];
            ea1[k] = eap[1];
        }
#pragma unroll
        for (int kk = 0; kk < 8; kk++) {
            float4 wv = s_w[kk * 8 + cg];
#pragma unroll
            for (int k = 0; k < 4; k++) {
                float evk;
                switch (kk) {
                    case 0: evk = ea0[k].x; break;
                    case 1: evk = ea0[k].y; break;
                    case 2: evk = ea0[k].z; break;
                    case 3: evk = ea0[k].w; break;
                    case 4: evk = ea1[k].x; break;
                    case 5: evk = ea1[k].y; break;
                    case 6: evk = ea1[k].z; break;
                    default: evk = ea1[k].w; break;
                }
                f4fma(y[k], evk, wv);
            }
        }
#pragma unroll
        for (int k = 0; k < 4; k++) {
            int e = (q0 + k) * 4 + es;
            store_h4(g_yh + (size_t)e * EMB + c0, y[k]);
            sum = f4add(sum, y[k]);
            ss.x = fmaf(y[k].x, y[k].x, ss.x);
            ss.y = fmaf(y[k].y, y[k].y, ss.y);
            ss.z = fmaf(y[k].z, y[k].z, ss.z);
            ss.w = fmaf(y[k].w, y[k].w, ss.w);
        }
    }
    stats_warp_to_shared(sum, ss, lane, c0, s_sum, s_ss);
    __syncthreads();
    if (tid < EMB) {
        atomicAdd(&g_stats[STAT_IDX(layer, 0, 0, tid)], s_sum[tid]);
        atomicAdd(&g_stats[STAT_IDX(layer, 0, 1, tid)], s_ss[tid]);
    }
}

// ---- E2 (register-blocked; writes y2 to CSR slot in g_yh2) -----------------
__global__ void __launch_bounds__(256) k_e2(const float* __restrict__ w2,
                     const float* __restrict__ b2,
                     const float* __restrict__ g1, const float* __restrict__ be1, int layer) {
    __shared__ float s_w2[EMB * EMB];
    __shared__ float s_sum[EMB], s_ss[EMB];
    int tid = threadIdx.x;
    for (int i = tid; i < EMB * EMB; i += 256) s_w2[i] = w2[i];
    if (tid < EMB) { s_sum[tid] = 0.f; s_ss[tid] = 0.f; }
    __syncthreads();
    int lane = tid & 31;
    int es = lane >> 3, cg = lane & 7, c0 = cg * 4, base = lane & 24;
    float sc[4], sh[4];
    bn_coeffs(layer, 0, 1.f / Ee, g1, be1, c0, sc, sh);
    float4 bb = *(const float4*)(b2 + c0);
    const float4* w2v = (const float4*)s_w2;
    int nw = gridDim.x * (blockDim.x >> 5);
    int gw = blockIdx.x * (blockDim.x >> 5) + (tid >> 5);
    float4 sum = make_float4(0, 0, 0, 0), ssq = make_float4(0, 0, 0, 0);
    const int NQ = Ee / 4;
    for (int q0 = gw * 4; q0 < NQ; q0 += nw * 4) {
        float m[4][4];
        float4 acc[4];
        int pe[4];
#pragma unroll
        for (int k = 0; k < 4; k++) {
            int e = (q0 + k) * 4 + es;
            pe[k] = g_pos[e];
            float4 y1 = load_h4(g_yh + (size_t)e * EMB + c0);
            m[k][0] = fmaxf(fmaf(y1.x, sc[0], sh[0]), 0.f);
            m[k][1] = fmaxf(fmaf(y1.y, sc[1], sh[1]), 0.f);
            m[k][2] = fmaxf(fmaf(y1.z, sc[2], sh[2]), 0.f);
            m[k][3] = fmaxf(fmaf(y1.w, sc[3], sh[3]), 0.f);
            acc[k] = bb;
        }
#pragma unroll
        for (int j = 0; j < EMB; j++) {
            float4 wv = w2v[j * 8 + cg];
#pragma unroll
            for (int k = 0; k < 4; k++) {
                float mj = __shfl_sync(0xffffffffu, m[k][j & 3], base + (j >> 2));
                f4fma(acc[k], mj, wv);
            }
        }
#pragma unroll
        for (int k = 0; k < 4; k++) {
            store_h4(g_yh2 + (size_t)pe[k] * EMB + c0, acc[k]);
            sum = f4add(sum, acc[k]);
            ssq.x = fmaf(acc[k].x, acc[k].x, ssq.x);
            ssq.y = fmaf(acc[k].y, acc[k].y, ssq.y);
            ssq.z = fmaf(acc[k].z, acc[k].z, ssq.z);
            ssq.w = fmaf(acc[k].w, acc[k].w, ssq.w);
        }
    }
    stats_warp_to_shared(sum, ssq, lane, c0, s_sum, s_ss);
    __syncthreads();
    if (tid < EMB) {
        atomicAdd(&g_stats[STAT_IDX(layer, 1, 0, tid)], s_sum[tid]);
        atomicAdd(&g_stats[STAT_IDX(layer, 1, 1, tid)], s_ss[tid]);
    }
}

// ---- fused E3+U1: aggr over CONTIGUOUS g_yh2 rows; y3; stats stage 2 -------
__global__ void __launch_bounds__(256) k_e3u1(const float* __restrict__ w,
                       const float* __restrict__ b,
                       const float* __restrict__ g2, const float* __restrict__ be2,
                       int layer) {
    __shared__ float sw[2 * EMB * EMB];
    __shared__ float s_sum[EMB], s_ss[EMB];
    int tid = threadIdx.x;
    for (int i = tid; i < 2 * EMB * EMB; i += 256) sw[i] = w[i];
    if (tid < EMB) { s_sum[tid] = 0.f; s_ss[tid] = 0.f; }
    __syncthreads();
    int lane = tid & 31;
    int es = lane >> 3, cg = lane & 7, c0 = cg * 4, base = lane & 24;
    float4 sum = make_float4(0, 0, 0, 0), ssq = make_float4(0, 0, 0, 0);

    int quad = blockIdx.x * 8 + (tid >> 5);
    if (quad * 4 < Nn) {
        float sc[4], sh[4];
        bn_coeffs(layer, 1, 1.f / Ee, g2, be2, c0, sc, sh);
        int n = quad * 4 + es;
        int rs = g_rowstart[n], re = g_rowstart[n + 1];
        float4 ag = make_float4(0, 0, 0, 0);
        for (int i = rs; i < re; i++) {
            float4 y = load_h4(g_yh2 + (size_t)i * EMB + c0);
            ag.x += fmaxf(fmaf(y.x, sc[0], sh[0]), 0.f);
            ag.y += fmaxf(fmaf(y.y, sc[1], sh[1]), 0.f);
            ag.z += fmaxf(fmaf(y.z, sc[2], sh[2]), 0.f);
            ag.w += fmaxf(fmaf(y.w, sc[3], sh[3]), 0.f);
        }
        float4 h4 = *(const float4*)(g_h + n * EMB + c0);
        float hr[4] = {h4.x, h4.y, h4.z, h4.w};
        float ar[4] = {ag.x, ag.y, ag.z, ag.w};
        const float4* swv = (const float4*)sw;
        float4 acc = *(const float4*)(b + c0);
#pragma unroll
        for (int j = 0; j < EMB; j++) {
            float hj = __shfl_sync(0xffffffffu, hr[j & 3], base + (j >> 2));
            f4fma(acc, hj, swv[j * 8 + cg]);
        }
#pragma unroll
        for (int j = 0; j < EMB; j++) {
            float aj = __shfl_sync(0xffffffffu, ar[j & 3], base + (j >> 2));
            f4fma(acc, aj, swv[(EMB + j) * 8 + cg]);
        }
        *(float4*)(g_y3 + n * EMB + c0) = acc;
        sum = acc;
        ssq.x = acc.x * acc.x; ssq.y = acc.y * acc.y;
        ssq.z = acc.z * acc.z; ssq.w = acc.w * acc.w;
    }
    stats_warp_to_shared(sum, ssq, lane, c0, s_sum, s_ss);
    __syncthreads();
    if (tid < EMB) {
        atomicAdd(&g_stats[STAT_IDX(layer, 2, 0, tid)], s_sum[tid]);
        atomicAdd(&g_stats[STAT_IDX(layer, 2, 1, tid)], s_ss[tid]);
    }
}

// ---------------- U2: r = relu(bn(y3)) ; y4 = r@Wu2+b ; stats stage 3 -------
__global__ void k_u2(const float* __restrict__ w2, const float* __restrict__ b2,
                     const float* __restrict__ g1, const float* __restrict__ be1, int layer) {
    __shared__ float s_w2[EMB * EMB];
    __shared__ float s_sum[EMB], s_ss[EMB];
    int tid = threadIdx.x;
    for (int i = tid; i < EMB * EMB; i += 256) s_w2[i] = w2[i];
    if (tid < EMB) { s_sum[tid] = 0.f; s_ss[tid] = 0.f; }
    __syncthreads();
    int lane = tid & 31;
    int es = lane >> 3, cg = lane & 7, c0 = cg * 4, base = lane & 24;
    float sc[4], sh[4];
    bn_coeffs(layer, 2, 1.f / Nn, g1, be1, c0, sc, sh);
    float4 bb = *(const float4*)(b2 + c0);
    const float4* w2v = (const float4*)s_w2;
    int nw = gridDim.x * (blockDim.x >> 5);
    int gw = blockIdx.x * (blockDim.x >> 5) + (tid >> 5);
    float4 sum = make_float4(0, 0, 0, 0), ssq = make_float4(0, 0, 0, 0);
    for (int qd = gw; qd < Nn / 4; qd += nw) {
        int n = qd * 4 + es;
        float4 y1 = *(const float4*)(g_y3 + n * EMB + c0);
        float m[4];
        m[0] = fmaxf(fmaf(y1.x, sc[0], sh[0]), 0.f);
        m[1] = fmaxf(fmaf(y1.y, sc[1], sh[1]), 0.f);
        m[2] = fmaxf(fmaf(y1.z, sc[2], sh[2]), 0.f);
        m[3] = fmaxf(fmaf(y1.w, sc[3], sh[3]), 0.f);
        float4 acc = bb;
#pragma unroll
        for (int j = 0; j < EMB; j++) {
            float mj = __shfl_sync(0xffffffffu, m[j & 3], base + (j >> 2));
            f4fma(acc, mj, w2v[j * 8 + cg]);
        }
        *(float4*)(g_y4 + n * EMB + c0) = acc;
        sum = f4add(sum, acc);
        ssq.x = fmaf(acc.x, acc.x, ssq.x); ssq.y = fmaf(acc.y, acc.y, ssq.y);
        ssq.z = fmaf(acc.z, acc.z, ssq.z); ssq.w = fmaf(acc.w, acc.w, ssq.w);
    }
    stats_warp_to_shared(sum, ssq, lane, c0, s_sum, s_ss);
    __syncthreads();
    if (tid < EMB) {
        atomicAdd(&g_stats[STAT_IDX(layer, 3, 0, tid)], s_sum[tid]);
        atomicAdd(&g_stats[STAT_IDX(layer, 3, 1, tid)], s_ss[tid]);
    }
}

// ---- final layer: h_final = h + relu(bn(y4)); pool atomics -----------------
__global__ void k_u3pool(const int* __restrict__ batch,
                         const float* __restrict__ g2, const float* __restrict__ be2,
                         int layer) {
    int idx = blockIdx.x * blockDim.x + threadIdx.x;
    if (idx >= Nn * 8) return;
    int n = idx >> 3, cg = idx & 7, c0 = cg * 4;
    float sc[4], sh[4];
    bn_coeffs(layer, 3, 1.f / Nn, g2, be2, c0, sc, sh);
    float4 y = *(const float4*)(g_y4 + n * EMB + c0);
    float4 h = *(const float4*)(g_h + n * EMB + c0);
    h.x += fmaxf(fmaf(y.x, sc[0], sh[0]), 0.f);
    h.y += fmaxf(fmaf(y.y, sc[1], sh[1]), 0.f);
    h.z += fmaxf(fmaf(y.z, sc[2], sh[2]), 0.f);
    h.w += fmaxf(fmaf(y.w, sc[3], sh[3]), 0.f);
    int b = batch[n];
    float* pp = g_pool + b * EMB + c0;
    atomicAdd(pp + 0, h.x); atomicAdd(pp + 1, h.y);
    atomicAdd(pp + 2, h.z); atomicAdd(pp + 3, h.w);
    if (cg == 0) atomicAdd(&g_cnt[b], 1.0f);
}

__global__ void k_pred(const float* __restrict__ pw, const float* __restrict__ pb,
                       float* __restrict__ out) {
    int t = threadIdx.x;
    if (t >= NB * NOUT) return;
    int b = t / NOUT, o = t % NOUT;
    float inv = 1.f / fmaxf(g_cnt[b], 1.f);
    float s = 0.f;
#pragma unroll
    for (int j = 0; j < EMB; j++) s = fmaf(g_pool[b * EMB + j], pw[j * NOUT + o], s);
    out[t] = pb[o] + s * inv;
}

// ---------------- launch -----------------------------------------------------
extern "C" void kernel_launch(void* const* d_in, const int* in_sizes, int n_in,
                              void* d_out, int out_size) {
    const float *x, *edge_attr, *lin_in_w, *lin_in_b;
    const float *msg_w1, *msg_b1, *msg_g1, *msg_be1, *msg_w2, *msg_b2, *msg_g2, *msg_be2;
    const float *upd_w1, *upd_b1, *upd_g1, *upd_be1, *upd_w2, *upd_b2, *upd_g2, *upd_be2;
    const float *pred_w, *pred_b;
    const int *edge_idx, *batch;

    if (in_sizes[1] == 2 * Ee) {
        x        = (const float*)d_in[0];
        edge_idx = (const int*)  d_in[1];
        edge_attr= (const float*)d_in[2];
        batch    = (const int*)  d_in[3];
        lin_in_w = (const float*)d_in[4];
        lin_in_b = (const float*)d_in[5];
        msg_w1   = (const float*)d_in[6];
        msg_b1   = (const float*)d_in[7];
        msg_g1   = (const float*)d_in[8];
        msg_be1  = (const float*)d_in[9];
        msg_w2   = (const float*)d_in[10];
        msg_b2   = (const float*)d_in[11];
        msg_g2   = (const float*)d_in[12];
        msg_be2  = (const float*)d_in[13];
        upd_w1   = (const float*)d_in[14];
        upd_b1   = (const float*)d_in[15];
        upd_g1   = (const float*)d_in[16];
        upd_be1  = (const float*)d_in[17];
        upd_w2   = (const float*)d_in[18];
        upd_b2   = (const float*)d_in[19];
        upd_g2   = (const float*)d_in[20];
        upd_be2  = (const float*)d_in[21];
        pred_w   = (const float*)d_in[22];
        pred_b   = (const float*)d_in[23];
    } else {
        x        = (const float*)d_in[0];
        edge_attr= (const float*)d_in[1];
        lin_in_w = (const float*)d_in[2];
        lin_in_b = (const float*)d_in[3];
        msg_w1   = (const float*)d_in[4];
        msg_b1   = (const float*)d_in[5];
        msg_g1   = (const float*)d_in[6];
        msg_be1  = (const float*)d_in[7];
        msg_w2   = (const float*)d_in[8];
        msg_b2   = (const float*)d_in[9];
        msg_g2   = (const float*)d_in[10];
        msg_be2  = (const float*)d_in[11];
        upd_w1   = (const float*)d_in[12];
        upd_b1   = (const float*)d_in[13];
        upd_g1   = (const float*)d_in[14];
        upd_be1  = (const float*)d_in[15];
        upd_w2   = (const float*)d_in[16];
        upd_b2   = (const float*)d_in[17];
        upd_g2   = (const float*)d_in[18];
        upd_be2  = (const float*)d_in[19];
        pred_w   = (const float*)d_in[20];
        pred_b   = (const float*)d_in[21];
        edge_idx = (const int*)  d_in[22];
        batch    = (const int*)  d_in[23];
    }
    float* out = (float*)d_out;

    // exact-wave grids for the big edge kernels (host-side query; capture-safe)
    int b1 = 4, b2 = 2;
    cudaOccupancyMaxActiveBlocksPerMultiprocessor(&b1, k_e1, 256, 0);
    cudaOccupancyMaxActiveBlocksPerMultiprocessor(&b2, k_e2, 256, 0);
    int grid_e1 = b1 * NSM, grid_e2 = b2 * NSM;

    // Launch order keeps k_e1 at capture index 3; CSR build completes before e2(l0).
    k_zero_once<<<NBLK_SCAN, 256>>>();
    k_linpq<<<Nn / 8, dim3(32, 8)>>>(x, lin_in_w, lin_in_b, msg_w1, msg_b1);
    k_hist<<<(Ee + 255) / 256, 256>>>(edge_idx);
    k_e1<<<grid_e1, 256>>>(edge_idx, edge_attr, msg_w1 + 2 * EMB * EMB, 0);
    k_scan1<<<NBLK_SCAN, 256>>>();
    k_scan2<<<1, 256>>>();
    k_scan3<<<NBLK_SCAN, 256>>>();
    k_fill<<<(Ee + 255) / 256, 256>>>(edge_idx);
    k_e2<<<grid_e2, 256>>>(msg_w2, msg_b2, msg_g1, msg_be1, 0);

    for (int l = 0; l < NL; l++) {
        const float* w1 = msg_w1 + l * (2 * EMB + ED) * EMB;
        if (l > 0) {
            k_u3pq<<<Nn / 8, dim3(32, 8)>>>(w1, msg_b1 + l * EMB,
                                            upd_g2 + (l - 1) * EMB, upd_be2 + (l - 1) * EMB,
                                            l - 1);
            k_e1<<<grid_e1, 256>>>(edge_idx, edge_attr, w1 + 2 * EMB * EMB, l);
            k_e2<<<grid_e2, 256>>>(msg_w2 + l * EMB * EMB, msg_b2 + l * EMB,
                                   msg_g1 + l * EMB, msg_be1 + l * EMB, l);
        }
        k_e3u1<<<(Nn / 4 + 7) / 8, 256>>>(upd_w1 + l * 2 * EMB * EMB, upd_b1 + l * EMB,
                                          msg_g2 + l * EMB, msg_be2 + l * EMB, l);
        k_u2<<<1184, 256>>>(upd_w2 + l * EMB * EMB, upd_b2 + l * EMB,
                            upd_g1 + l * EMB, upd_be1 + l * EMB, l);
    }
    k_u3pool<<<(Nn * 8 + 255) / 256, 256>>>(batch, upd_g2 + (NL - 1) * EMB,
                                            upd_be2 + (NL - 1) * EMB, NL - 1);
    k_pred<<<1, NB * NOUT>>>(pred_w, pred_b, out);
}

// round 15
// speedup vs baseline: 1.5848x; 1.1619x over previous
#include <cuda_runtime.h>
#include <cuda_fp16.h>
#include <cstdint>

#define Nn    50000
#define Ee    800000
#define INDIM 128
#define EMB   32
#define ED    8
#define NL    4
#define NB    64
#define NOUT  10
#define EPS_BN 1e-5f
#define NBLK_SCAN 196   // ceil(Nn/256)
#define NSM   148

// ---------------- scratch (device globals) ----------------------------------
__device__ __align__(16) float  g_h[Nn * EMB];
__device__ __align__(16) float  g_p[Nn * EMB];
__device__ __align__(16) float  g_q[Nn * EMB];
__device__ __align__(16) float  g_y3[Nn * EMB];
__device__ __align__(16) float  g_y4[Nn * EMB];
__device__ __align__(16) __half g_yh[(size_t)Ee * EMB];   // y1, fp16, edge order
__device__ __align__(16) __half g_yh2[(size_t)Ee * EMB];  // y2, fp16, CSR order
__device__ __align__(16) float  g_stats[NL * 4 * 2 * EMB];
__device__ __align__(16) float  g_pool[NB * EMB];
__device__ __align__(16) float  g_cnt[NB];
// CSR (built once per launch; dst is launch-invariant)
__device__ int g_deg[Nn];
__device__ int g_rowstart[Nn + 1];
__device__ int g_cursor[Nn];
__device__ int g_pos[Ee];        // edge -> CSR slot
__device__ int g_bsum[NBLK_SCAN];
__device__ int g_boff[NBLK_SCAN];

#define STAT_IDX(l, stage, which, c) ((((l) * 4 + (stage)) * 2 + (which)) * EMB + (c))

// ---------------- helpers ---------------------------------------------------
__device__ __forceinline__ float4 f4add(float4 a, float4 b) {
    return make_float4(a.x + b.x, a.y + b.y, a.z + b.z, a.w + b.w);
}
__device__ __forceinline__ void f4fma(float4& a, float s, float4 w) {
    a.x = fmaf(s, w.x, a.x); a.y = fmaf(s, w.y, a.y);
    a.z = fmaf(s, w.z, a.z); a.w = fmaf(s, w.w, a.w);
}
__device__ __forceinline__ void store_h4(__half* p, float4 v) {
    union { __half2 h[2]; uint2 u; } cv;
    cv.h[0] = __float22half2_rn(make_float2(v.x, v.y));
    cv.h[1] = __float22half2_rn(make_float2(v.z, v.w));
    *(uint2*)p = cv.u;
}
__device__ __forceinline__ float4 load_h4(const __half* p) {
    union { uint2 u; __half2 h[2]; } cv;
    cv.u = *(const uint2*)p;
    float2 a = __half22float2(cv.h[0]);
    float2 b = __half22float2(cv.h[1]);
    return make_float4(a.x, a.y, b.x, b.y);
}
__device__ __forceinline__ uint32_t h2_to_u32(__half2 v) {
    union { __half2 h; uint32_t u; } cv; cv.h = v; return cv.u;
}
__device__ __forceinline__ void ldm_x4(uint32_t addr, uint32_t& r0, uint32_t& r1,
                                       uint32_t& r2, uint32_t& r3) {
    asm volatile("ldmatrix.sync.aligned.m8n8.x4.shared.b16 {%0,%1,%2,%3}, [%4];"
                 : "=r"(r0), "=r"(r1), "=r"(r2), "=r"(r3) : "r"(addr));
}
__device__ __forceinline__ void mma16816(float& c0, float& c1, float& c2, float& c3,
                                         uint32_t a0, uint32_t a1, uint32_t a2, uint32_t a3,
                                         uint32_t b0, uint32_t b1) {
    asm volatile("mma.sync.aligned.m16n8k16.row.col.f32.f16.f16.f32 "
                 "{%0,%1,%2,%3}, {%4,%5,%6,%7}, {%8,%9}, {%0,%1,%2,%3};"
                 : "+f"(c0), "+f"(c1), "+f"(c2), "+f"(c3)
                 : "r"(a0), "r"(a1), "r"(a2), "r"(a3), "r"(b0), "r"(b1));
}

__device__ __forceinline__ void stats_warp_to_shared(float4 sum, float4 ss, int lane,
                                                     int c0, float* s_sum, float* s_ss) {
#pragma unroll
    for (int off = 8; off < 32; off <<= 1) {
        sum.x += __shfl_xor_sync(0xffffffffu, sum.x, off);
        sum.y += __shfl_xor_sync(0xffffffffu, sum.y, off);
        sum.z += __shfl_xor_sync(0xffffffffu, sum.z, off);
        sum.w += __shfl_xor_sync(0xffffffffu, sum.w, off);
        ss.x  += __shfl_xor_sync(0xffffffffu, ss.x, off);
        ss.y  += __shfl_xor_sync(0xffffffffu, ss.y, off);
        ss.z  += __shfl_xor_sync(0xffffffffu, ss.z, off);
        ss.w  += __shfl_xor_sync(0xffffffffu, ss.w, off);
    }
    if (lane < 8) {
        atomicAdd(&s_sum[c0 + 0], sum.x); atomicAdd(&s_sum[c0 + 1], sum.y);
        atomicAdd(&s_sum[c0 + 2], sum.z); atomicAdd(&s_sum[c0 + 3], sum.w);
        atomicAdd(&s_ss[c0 + 0], ss.x);   atomicAdd(&s_ss[c0 + 1], ss.y);
        atomicAdd(&s_ss[c0 + 2], ss.z);   atomicAdd(&s_ss[c0 + 3], ss.w);
    }
}

__device__ __forceinline__ void bn_coeffs(int l, int stage, float inv_n,
                                          const float* __restrict__ gamma,
                                          const float* __restrict__ beta,
                                          int c0, float sc[4], float sh[4]) {
#pragma unroll
    for (int i = 0; i < 4; i++) {
        int c = c0 + i;
        float s1 = g_stats[STAT_IDX(l, stage, 0, c)];
        float s2 = g_stats[STAT_IDX(l, stage, 1, c)];
        float mu = s1 * inv_n;
        float var = s2 * inv_n - mu * mu;
        float rs = rsqrtf(var + EPS_BN);
        sc[i] = rs * gamma[c];
        sh[i] = beta[c] - mu * sc[i];
    }
}

// ---------------- init + CSR build ------------------------------------------
__global__ void k_zero_once() {
    int i = blockIdx.x * blockDim.x + threadIdx.x;
    if (i < NL * 4 * 2 * EMB) g_stats[i] = 0.f;
    if (i < NB * EMB) g_pool[i] = 0.f;
    if (i < NB) g_cnt[i] = 0.f;
    if (i < Nn) g_deg[i] = 0;
}
__global__ void k_hist(const int* __restrict__ ei) {
    int i = blockIdx.x * blockDim.x + threadIdx.x;
    if (i < Ee) atomicAdd(&g_deg[ei[Ee + i]], 1);
}
__global__ void k_scan1() {
    __shared__ int s[256];
    int t = threadIdx.x;
    int i = blockIdx.x * 256 + t;
    int v = (i < Nn) ? g_deg[i] : 0;
    s[t] = v;
    __syncthreads();
#pragma unroll
    for (int off = 1; off < 256; off <<= 1) {
        int add = (t >= off) ? s[t - off] : 0;
        __syncthreads();
        s[t] += add;
        __syncthreads();
    }
    if (i < Nn) g_rowstart[i + 1] = s[t];
    if (t == 255) g_bsum[blockIdx.x] = s[255];
}
__global__ void k_scan2() {
    __shared__ int s[256];
    int t = threadIdx.x;
    int v = (t < NBLK_SCAN) ? g_bsum[t] : 0;
    s[t] = v;
    __syncthreads();
#pragma unroll
    for (int off = 1; off < 256; off <<= 1) {
        int add = (t >= off) ? s[t - off] : 0;
        __syncthreads();
        s[t] += add;
        __syncthreads();
    }
    if (t < NBLK_SCAN) g_boff[t] = s[t] - v;   // exclusive
}
__global__ void k_scan3() {
    int i = blockIdx.x * blockDim.x + threadIdx.x;
    if (i < Nn) {
        int v = g_rowstart[i + 1] + g_boff[i >> 8];
        g_rowstart[i + 1] = v;
        g_cursor[i] = v - g_deg[i];
    }
    if (i == 0) g_rowstart[0] = 0;
}
__global__ void k_fill(const int* __restrict__ ei) {
    int i = blockIdx.x * blockDim.x + threadIdx.x;
    if (i < Ee) {
        int d = ei[Ee + i];
        g_pos[i] = atomicAdd(&g_cursor[d], 1);
    }
}

// ---- fused lin_in + pq(layer0) ----------------------------------------------
__global__ void k_linpq(const float* __restrict__ x, const float* __restrict__ w,
                        const float* __restrict__ b,
                        const float* __restrict__ w1, const float* __restrict__ b1) {
    __shared__ float ws[INDIM * EMB];
    __shared__ float xs[8][INDIM];
    __shared__ float wd[EMB * EMB];
    __shared__ float wsr[EMB * EMB];
    __shared__ float hs[8][EMB];
    int tx = threadIdx.x, ty = threadIdx.y;
    int tid = ty * 32 + tx;
    for (int i = tid; i < INDIM * EMB; i += 256) ws[i] = w[i];
    for (int i = tid; i < EMB * EMB; i += 256) { wd[i] = w1[i]; wsr[i] = w1[EMB * EMB + i]; }
    int base = blockIdx.x * 8;
    for (int i = tid; i < 8 * INDIM; i += 256) {
        int nloc = i >> 7, k = i & 127;
        xs[nloc][k] = x[(base + nloc) * INDIM + k];
    }
    __syncthreads();
    float acc = b[tx];
#pragma unroll 8
    for (int k = 0; k < INDIM; k++) acc = fmaf(xs[ty][k], ws[k * EMB + tx], acc);
    int n = base + ty;
    g_h[n * EMB + tx] = acc;
    hs[ty][tx] = acc;
    __syncthreads();
    float ap = b1[tx], aq = 0.f;
#pragma unroll
    for (int k = 0; k < EMB; k++) {
        float hv = hs[ty][k];
        ap = fmaf(hv, wd[k * EMB + tx], ap);
        aq = fmaf(hv, wsr[k * EMB + tx], aq);
    }
    g_p[n * EMB + tx] = ap;
    g_q[n * EMB + tx] = aq;
}

// ---- fused u3(prev layer) + pq(this layer) ---------------------------------
__global__ void k_u3pq(const float* __restrict__ w1, const float* __restrict__ b1,
                       const float* __restrict__ g2, const float* __restrict__ be2,
                       int prev) {
    __shared__ float wd[EMB * EMB];
    __shared__ float wsr[EMB * EMB];
    __shared__ float hs[8][EMB];
    int tx = threadIdx.x, ty = threadIdx.y;
    int tid = ty * 32 + tx;
    for (int i = tid; i < EMB * EMB; i += 256) { wd[i] = w1[i]; wsr[i] = w1[EMB * EMB + i]; }
    float s1 = g_stats[STAT_IDX(prev, 3, 0, tx)];
    float s2 = g_stats[STAT_IDX(prev, 3, 1, tx)];
    float mu = s1 * (1.f / Nn);
    float var = s2 * (1.f / Nn) - mu * mu;
    float rs = rsqrtf(var + EPS_BN);
    float sc = rs * g2[tx];
    float sh = be2[tx] - mu * sc;
    int base = blockIdx.x * 8;
    int n = base + ty;
    float hv = g_h[n * EMB + tx] + fmaxf(fmaf(g_y4[n * EMB + tx], sc, sh), 0.f);
    g_h[n * EMB + tx] = hv;
    hs[ty][tx] = hv;
    __syncthreads();
    float ap = b1[tx], aq = 0.f;
#pragma unroll
    for (int k = 0; k < EMB; k++) {
        float h2 = hs[ty][k];
        ap = fmaf(h2, wd[k * EMB + tx], ap);
        aq = fmaf(h2, wsr[k * EMB + tx], aq);
    }
    g_p[n * EMB + tx] = ap;
    g_q[n * EMB + tx] = aq;
}

// ---- E1 (register-blocked, 4 quads per weight pass) ------------------------
__global__ void __launch_bounds__(256) k_e1(const int* __restrict__ ei,
                     const float* __restrict__ ea,
                     const float* __restrict__ wc, int layer) {
    __shared__ float4 s_w[64];      // [k][cg]
    __shared__ float s_sum[EMB], s_ss[EMB];
    int tid = threadIdx.x;
    if (tid < 64) s_w[tid] = *(const float4*)(wc + (tid >> 3) * EMB + (tid & 7) * 4);
    if (tid < EMB) { s_sum[tid] = 0.f; s_ss[tid] = 0.f; }
    __syncthreads();
    int lane = tid & 31;
    int es = lane >> 3, cg = lane & 7, c0 = cg * 4;
    int nw = gridDim.x * (blockDim.x >> 5);
    int gw = blockIdx.x * (blockDim.x >> 5) + (tid >> 5);
    float4 sum = make_float4(0, 0, 0, 0), ss = make_float4(0, 0, 0, 0);
    const int NQ = Ee / 4;
    for (int q0 = gw * 4; q0 < NQ; q0 += nw * 4) {
        float4 y[4], ea0[4], ea1[4];
#pragma unroll
        for (int k = 0; k < 4; k++) {
            int e = (q0 + k) * 4 + es;
            int s = ei[e], d = ei[Ee + e];
            float4 pv = *(const float4*)(g_p + d * EMB + c0);
            float4 qv = *(const float4*)(g_q + s * EMB + c0);
            y[k] = f4add(pv, qv);
            const float4* eap = (const float4*)(ea + (size_t)e * ED);
            ea0[k] = eap[0];
            ea1[k] = eap[1];
        }
#pragma unroll
        for (int kk = 0; kk < 8; kk++) {
            float4 wv = s_w[kk * 8 + cg];
#pragma unroll
            for (int k = 0; k < 4; k++) {
                float evk;
                switch (kk) {
                    case 0: evk = ea0[k].x; break;
                    case 1: evk = ea0[k].y; break;
                    case 2: evk = ea0[k].z; break;
                    case 3: evk = ea0[k].w; break;
                    case 4: evk = ea1[k].x; break;
                    case 5: evk = ea1[k].y; break;
                    case 6: evk = ea1[k].z; break;
                    default: evk = ea1[k].w; break;
                }
                f4fma(y[k], evk, wv);
            }
        }
#pragma unroll
        for (int k = 0; k < 4; k++) {
            int e = (q0 + k) * 4 + es;
            store_h4(g_yh + (size_t)e * EMB + c0, y[k]);
            sum = f4add(sum, y[k]);
            ss.x = fmaf(y[k].x, y[k].x, ss.x);
            ss.y = fmaf(y[k].y, y[k].y, ss.y);
            ss.z = fmaf(y[k].z, y[k].z, ss.z);
            ss.w = fmaf(y[k].w, y[k].w, ss.w);
        }
    }
    stats_warp_to_shared(sum, ss, lane, c0, s_sum, s_ss);
    __syncthreads();
    if (tid < EMB) {
        atomicAdd(&g_stats[STAT_IDX(layer, 0, 0, tid)], s_sum[tid]);
        atomicAdd(&g_stats[STAT_IDX(layer, 0, 1, tid)], s_ss[tid]);
    }
}

// ---- E2 (tensor-core): m1 = relu(bn(y1)) fp16; y2 = m1@W2+b2 via HMMA ------
// 16 consecutive edges per warp-iteration; writes y2 to CSR slot; stats stage 1.
#define TROW 40   // halves per smem tile row (80B stride; 16B pad kills ldmatrix conflicts)
__global__ void __launch_bounds__(256) k_e2(const float* __restrict__ w2,
                     const float* __restrict__ b2,
                     const float* __restrict__ g1, const float* __restrict__ be1, int layer) {
    __shared__ __align__(16) __half s_tile[8][16 * TROW];
    __shared__ float s_sum[EMB], s_ss[EMB];
    int tid = threadIdx.x;
    int wid = tid >> 5, lane = tid & 31;
    if (tid < EMB) { s_sum[tid] = 0.f; s_ss[tid] = 0.f; }
    __syncthreads();
    int es = lane >> 3, cg = lane & 7, c0 = cg * 4;
    int m4 = lane & 3, qr = lane >> 2;            // mma col-pair / row-group ids
    float sc[4], sh[4];
    bn_coeffs(layer, 0, 1.f / Ee, g1, be1, c0, sc, sh);
    // B fragments from W2 (fp32 -> fp16), per PTX m16n8k16 col-B lane mapping
    uint32_t Bf[4][2][2];
#pragma unroll
    for (int nt = 0; nt < 4; nt++)
#pragma unroll
        for (int ks = 0; ks < 2; ks++)
#pragma unroll
            for (int r = 0; r < 2; r++) {
                int k0 = ks * 16 + r * 8 + 2 * m4;
                int c  = nt * 8 + qr;
                Bf[nt][ks][r] = h2_to_u32(__floats2half2_rn(w2[k0 * EMB + c],
                                                            w2[(k0 + 1) * EMB + c]));
            }
    float bias0[4], bias1[4];
#pragma unroll
    for (int nt = 0; nt < 4; nt++) {
        bias0[nt] = b2[nt * 8 + 2 * m4];
        bias1[nt] = b2[nt * 8 + 2 * m4 + 1];
    }
    float sums[8] = {0, 0, 0, 0, 0, 0, 0, 0};
    float ssqs[8] = {0, 0, 0, 0, 0, 0, 0, 0};
    uint32_t tb = (uint32_t)__cvta_generic_to_shared(&s_tile[wid][0]);
    uint32_t ld_addr = tb + (uint32_t)((lane & 15) * (TROW * 2)) + ((lane & 16) ? 16u : 0u);
    int nw = gridDim.x * (blockDim.x >> 5);
    int gw = blockIdx.x * (blockDim.x >> 5) + wid;
    const int NT = Ee / 16;   // 50000
    for (int t = gw; t < NT; t += nw) {
        int e0 = t * 16;
        int pos_lo = g_pos[e0 + qr];
        int pos_hi = g_pos[e0 + 8 + qr];
        // compute m (fp32 BN+relu) and stash fp16 tile
#pragma unroll
        for (int k = 0; k < 4; k++) {
            int row = k * 4 + es;
            float4 y1 = load_h4(g_yh + (size_t)(e0 + row) * EMB + c0);
            float m0 = fmaxf(fmaf(y1.x, sc[0], sh[0]), 0.f);
            float m1 = fmaxf(fmaf(y1.y, sc[1], sh[1]), 0.f);
            float m2 = fmaxf(fmaf(y1.z, sc[2], sh[2]), 0.f);
            float m3 = fmaxf(fmaf(y1.w, sc[3], sh[3]), 0.f);
            union { __half2 h[2]; uint2 u; } cv;
            cv.h[0] = __floats2half2_rn(m0, m1);
            cv.h[1] = __floats2half2_rn(m2, m3);
            *(uint2*)&s_tile[wid][row * TROW + cg * 4] = cv.u;
        }
        __syncwarp();
        uint32_t a0, a1, a2, a3, a4, a5, a6, a7;
        ldm_x4(ld_addr,       a0, a1, a2, a3);   // k = 0..15
        ldm_x4(ld_addr + 32u, a4, a5, a6, a7);   // k = 16..31
        __syncwarp();
#pragma unroll
        for (int nt = 0; nt < 4; nt++) {
            float cf0 = 0.f, cf1 = 0.f, cf2 = 0.f, cf3 = 0.f;
            mma16816(cf0, cf1, cf2, cf3, a0, a1, a2, a3, Bf[nt][0][0], Bf[nt][0][1]);
            mma16816(cf0, cf1, cf2, cf3, a4, a5, a6, a7, Bf[nt][1][0], Bf[nt][1][1]);
            cf0 += bias0[nt]; cf1 += bias1[nt];
            cf2 += bias0[nt]; cf3 += bias1[nt];
            sums[nt * 2 + 0] += cf0 + cf2;
            sums[nt * 2 + 1] += cf1 + cf3;
            ssqs[nt * 2 + 0] += cf0 * cf0 + cf2 * cf2;
            ssqs[nt * 2 + 1] += cf1 * cf1 + cf3 * cf3;
            int coff = nt * 8 + 2 * m4;
            *(__half2*)(g_yh2 + (size_t)pos_lo * EMB + coff) = __floats2half2_rn(cf0, cf1);
            *(__half2*)(g_yh2 + (size_t)pos_hi * EMB + coff) = __floats2half2_rn(cf2, cf3);
        }
    }
    // reduce stats across the 8 lanes sharing m4 (xor over qr bits)
#pragma unroll
    for (int off = 4; off < 32; off <<= 1)
#pragma unroll
        for (int i = 0; i < 8; i++) {
            sums[i] += __shfl_xor_sync(0xffffffffu, sums[i], off);
            ssqs[i] += __shfl_xor_sync(0xffffffffu, ssqs[i], off);
        }
    if (lane < 4) {
#pragma unroll
        for (int nt = 0; nt < 4; nt++) {
#pragma unroll
            for (int d = 0; d < 2; d++) {
                int col = nt * 8 + 2 * lane + d;
                atomicAdd(&s_sum[col], sums[nt * 2 + d]);
                atomicAdd(&s_ss[col],  ssqs[nt * 2 + d]);
            }
        }
    }
    __syncthreads();
    if (tid < EMB) {
        atomicAdd(&g_stats[STAT_IDX(layer, 1, 0, tid)], s_sum[tid]);
        atomicAdd(&g_stats[STAT_IDX(layer, 1, 1, tid)], s_ss[tid]);
    }
}

// ---- fused E3+U1: aggr over CONTIGUOUS g_yh2 rows; y3; stats stage 2 -------
__global__ void __launch_bounds__(256) k_e3u1(const float* __restrict__ w,
                       const float* __restrict__ b,
                       const float* __restrict__ g2, const float* __restrict__ be2,
                       int layer) {
    __shared__ float sw[2 * EMB * EMB];
    __shared__ float s_sum[EMB], s_ss[EMB];
    int tid = threadIdx.x;
    for (int i = tid; i < 2 * EMB * EMB; i += 256) sw[i] = w[i];
    if (tid < EMB) { s_sum[tid] = 0.f; s_ss[tid] = 0.f; }
    __syncthreads();
    int lane = tid & 31;
    int es = lane >> 3, cg = lane & 7, c0 = cg * 4, base = lane & 24;
    float4 sum = make_float4(0, 0, 0, 0), ssq = make_float4(0, 0, 0, 0);

    int quad = blockIdx.x * 8 + (tid >> 5);
    if (quad * 4 < Nn) {
        float sc[4], sh[4];
        bn_coeffs(layer, 1, 1.f / Ee, g2, be2, c0, sc, sh);
        int n = quad * 4 + es;
        int rs = g_rowstart[n], re = g_rowstart[n + 1];
        float4 ag = make_float4(0, 0, 0, 0);
        for (int i = rs; i < re; i++) {
            float4 y = load_h4(g_yh2 + (size_t)i * EMB + c0);
            ag.x += fmaxf(fmaf(y.x, sc[0], sh[0]), 0.f);
            ag.y += fmaxf(fmaf(y.y, sc[1], sh[1]), 0.f);
            ag.z += fmaxf(fmaf(y.z, sc[2], sh[2]), 0.f);
            ag.w += fmaxf(fmaf(y.w, sc[3], sh[3]), 0.f);
        }
        float4 h4 = *(const float4*)(g_h + n * EMB + c0);
        float hr[4] = {h4.x, h4.y, h4.z, h4.w};
        float ar[4] = {ag.x, ag.y, ag.z, ag.w};
        const float4* swv = (const float4*)sw;
        float4 acc = *(const float4*)(b + c0);
#pragma unroll
        for (int j = 0; j < EMB; j++) {
            float hj = __shfl_sync(0xffffffffu, hr[j & 3], base + (j >> 2));
            f4fma(acc, hj, swv[j * 8 + cg]);
        }
#pragma unroll
        for (int j = 0; j < EMB; j++) {
            float aj = __shfl_sync(0xffffffffu, ar[j & 3], base + (j >> 2));
            f4fma(acc, aj, swv[(EMB + j) * 8 + cg]);
        }
        *(float4*)(g_y3 + n * EMB + c0) = acc;
        sum = acc;
        ssq.x = acc.x * acc.x; ssq.y = acc.y * acc.y;
        ssq.z = acc.z * acc.z; ssq.w = acc.w * acc.w;
    }
    stats_warp_to_shared(sum, ssq, lane, c0, s_sum, s_ss);
    __syncthreads();
    if (tid < EMB) {
        atomicAdd(&g_stats[STAT_IDX(layer, 2, 0, tid)], s_sum[tid]);
        atomicAdd(&g_stats[STAT_IDX(layer, 2, 1, tid)], s_ss[tid]);
    }
}

// ---------------- U2: r = relu(bn(y3)) ; y4 = r@Wu2+b ; stats stage 3 -------
__global__ void k_u2(const float* __restrict__ w2, const float* __restrict__ b2,
                     const float* __restrict__ g1, const float* __restrict__ be1, int layer) {
    __shared__ float s_w2[EMB * EMB];
    __shared__ float s_sum[EMB], s_ss[EMB];
    int tid = threadIdx.x;
    for (int i = tid; i < EMB * EMB; i += 256) s_w2[i] = w2[i];
    if (tid < EMB) { s_sum[tid] = 0.f; s_ss[tid] = 0.f; }
    __syncthreads();
    int lane = tid & 31;
    int es = lane >> 3, cg = lane & 7, c0 = cg * 4, base = lane & 24;
    float sc[4], sh[4];
    bn_coeffs(layer, 2, 1.f / Nn, g1, be1, c0, sc, sh);
    float4 bb = *(const float4*)(b2 + c0);
    const float4* w2v = (const float4*)s_w2;
    int nw = gridDim.x * (blockDim.x >> 5);
    int gw = blockIdx.x * (blockDim.x >> 5) + (tid >> 5);
    float4 sum = make_float4(0, 0, 0, 0), ssq = make_float4(0, 0, 0, 0);
    for (int qd = gw; qd < Nn / 4; qd += nw) {
        int n = qd * 4 + es;
        float4 y1 = *(const float4*)(g_y3 + n * EMB + c0);
        float m[4];
        m[0] = fmaxf(fmaf(y1.x, sc[0], sh[0]), 0.f);
        m[1] = fmaxf(fmaf(y1.y, sc[1], sh[1]), 0.f);
        m[2] = fmaxf(fmaf(y1.z, sc[2], sh[2]), 0.f);
        m[3] = fmaxf(fmaf(y1.w, sc[3], sh[3]), 0.f);
        float4 acc = bb;
#pragma unroll
        for (int j = 0; j < EMB; j++) {
            float mj = __shfl_sync(0xffffffffu, m[j & 3], base + (j >> 2));
            f4fma(acc, mj, w2v[j * 8 + cg]);
        }
        *(float4*)(g_y4 + n * EMB + c0) = acc;
        sum = f4add(sum, acc);
        ssq.x = fmaf(acc.x, acc.x, ssq.x); ssq.y = fmaf(acc.y, acc.y, ssq.y);
        ssq.z = fmaf(acc.z, acc.z, ssq.z); ssq.w = fmaf(acc.w, acc.w, ssq.w);
    }
    stats_warp_to_shared(sum, ssq, lane, c0, s_sum, s_ss);
    __syncthreads();
    if (tid < EMB) {
        atomicAdd(&g_stats[STAT_IDX(layer, 3, 0, tid)], s_sum[tid]);
        atomicAdd(&g_stats[STAT_IDX(layer, 3, 1, tid)], s_ss[tid]);
    }
}

// ---- final layer: h_final = h + relu(bn(y4)); pool atomics -----------------
__global__ void k_u3pool(const int* __restrict__ batch,
                         const float* __restrict__ g2, const float* __restrict__ be2,
                         int layer) {
    int idx = blockIdx.x * blockDim.x + threadIdx.x;
    if (idx >= Nn * 8) return;
    int n = idx >> 3, cg = idx & 7, c0 = cg * 4;
    float sc[4], sh[4];
    bn_coeffs(layer, 3, 1.f / Nn, g2, be2, c0, sc, sh);
    float4 y = *(const float4*)(g_y4 + n * EMB + c0);
    float4 h = *(const float4*)(g_h + n * EMB + c0);
    h.x += fmaxf(fmaf(y.x, sc[0], sh[0]), 0.f);
    h.y += fmaxf(fmaf(y.y, sc[1], sh[1]), 0.f);
    h.z += fmaxf(fmaf(y.z, sc[2], sh[2]), 0.f);
    h.w += fmaxf(fmaf(y.w, sc[3], sh[3]), 0.f);
    int b = batch[n];
    float* pp = g_pool + b * EMB + c0;
    atomicAdd(pp + 0, h.x); atomicAdd(pp + 1, h.y);
    atomicAdd(pp + 2, h.z); atomicAdd(pp + 3, h.w);
    if (cg == 0) atomicAdd(&g_cnt[b], 1.0f);
}

__global__ void k_pred(const float* __restrict__ pw, const float* __restrict__ pb,
                       float* __restrict__ out) {
    int t = threadIdx.x;
    if (t >= NB * NOUT) return;
    int b = t / NOUT, o = t % NOUT;
    float inv = 1.f / fmaxf(g_cnt[b], 1.f);
    float s = 0.f;
#pragma unroll
    for (int j = 0; j < EMB; j++) s = fmaf(g_pool[b * EMB + j], pw[j * NOUT + o], s);
    out[t] = pb[o] + s * inv;
}

// ---------------- launch -----------------------------------------------------
extern "C" void kernel_launch(void* const* d_in, const int* in_sizes, int n_in,
                              void* d_out, int out_size) {
    const float *x, *edge_attr, *lin_in_w, *lin_in_b;
    const float *msg_w1, *msg_b1, *msg_g1, *msg_be1, *msg_w2, *msg_b2, *msg_g2, *msg_be2;
    const float *upd_w1, *upd_b1, *upd_g1, *upd_be1, *upd_w2, *upd_b2, *upd_g2, *upd_be2;
    const float *pred_w, *pred_b;
    const int *edge_idx, *batch;

    if (in_sizes[1] == 2 * Ee) {
        x        = (const float*)d_in[0];
        edge_idx = (const int*)  d_in[1];
        edge_attr= (const float*)d_in[2];
        batch    = (const int*)  d_in[3];
        lin_in_w = (const float*)d_in[4];
        lin_in_b = (const float*)d_in[5];
        msg_w1   = (const float*)d_in[6];
        msg_b1   = (const float*)d_in[7];
        msg_g1   = (const float*)d_in[8];
        msg_be1  = (const float*)d_in[9];
        msg_w2   = (const float*)d_in[10];
        msg_b2   = (const float*)d_in[11];
        msg_g2   = (const float*)d_in[12];
        msg_be2  = (const float*)d_in[13];
        upd_w1   = (const float*)d_in[14];
        upd_b1   = (const float*)d_in[15];
        upd_g1   = (const float*)d_in[16];
        upd_be1  = (const float*)d_in[17];
        upd_w2   = (const float*)d_in[18];
        upd_b2   = (const float*)d_in[19];
        upd_g2   = (const float*)d_in[20];
        upd_be2  = (const float*)d_in[21];
        pred_w   = (const float*)d_in[22];
        pred_b   = (const float*)d_in[23];
    } else {
        x        = (const float*)d_in[0];
        edge_attr= (const float*)d_in[1];
        lin_in_w = (const float*)d_in[2];
        lin_in_b = (const float*)d_in[3];
        msg_w1   = (const float*)d_in[4];
        msg_b1   = (const float*)d_in[5];
        msg_g1   = (const float*)d_in[6];
        msg_be1  = (const float*)d_in[7];
        msg_w2   = (const float*)d_in[8];
        msg_b2   = (const float*)d_in[9];
        msg_g2   = (const float*)d_in[10];
        msg_be2  = (const float*)d_in[11];
        upd_w1   = (const float*)d_in[12];
        upd_b1   = (const float*)d_in[13];
        upd_g1   = (const float*)d_in[14];
        upd_be1  = (const float*)d_in[15];
        upd_w2   = (const float*)d_in[16];
        upd_b2   = (const float*)d_in[17];
        upd_g2   = (const float*)d_in[18];
        upd_be2  = (const float*)d_in[19];
        pred_w   = (const float*)d_in[20];
        pred_b   = (const float*)d_in[21];
        edge_idx = (const int*)  d_in[22];
        batch    = (const int*)  d_in[23];
    }
    float* out = (float*)d_out;

    // exact-wave grids for the big edge kernels (host-side query; capture-safe)
    int b1 = 4, b2q = 2;
    cudaOccupancyMaxActiveBlocksPerMultiprocessor(&b1, k_e1, 256, 0);
    cudaOccupancyMaxActiveBlocksPerMultiprocessor(&b2q, k_e2, 256, 0);
    int grid_e1 = b1 * NSM, grid_e2 = b2q * NSM;

    // Launch order keeps k_e1 at capture index 3; CSR build completes before e2(l0).
    k_zero_once<<<NBLK_SCAN, 256>>>();
    k_linpq<<<Nn / 8, dim3(32, 8)>>>(x, lin_in_w, lin_in_b, msg_w1, msg_b1);
    k_hist<<<(Ee + 255) / 256, 256>>>(edge_idx);
    k_e1<<<grid_e1, 256>>>(edge_idx, edge_attr, msg_w1 + 2 * EMB * EMB, 0);
    k_scan1<<<NBLK_SCAN, 256>>>();
    k_scan2<<<1, 256>>>();
    k_scan3<<<NBLK_SCAN, 256>>>();
    k_fill<<<(Ee + 255) / 256, 256>>>(edge_idx);
    k_e2<<<grid_e2, 256>>>(msg_w2, msg_b2, msg_g1, msg_be1, 0);

    for (int l = 0; l < NL; l++) {
        const float* w1 = msg_w1 + l * (2 * EMB + ED) * EMB;
        if (l > 0) {
            k_u3pq<<<Nn / 8, dim3(32, 8)>>>(w1, msg_b1 + l * EMB,
                                            upd_g2 + (l - 1) * EMB, upd_be2 + (l - 1) * EMB,
                                            l - 1);
            k_e1<<<grid_e1, 256>>>(edge_idx, edge_attr, w1 + 2 * EMB * EMB, l);
            k_e2<<<grid_e2, 256>>>(msg_w2 + l * EMB * EMB, msg_b2 + l * EMB,
                                   msg_g1 + l * EMB, msg_be1 + l * EMB, l);
        }
        k_e3u1<<<(Nn / 4 + 7) / 8, 256>>>(upd_w1 + l * 2 * EMB * EMB, upd_b1 + l * EMB,
                                          msg_g2 + l * EMB, msg_be2 + l * EMB, l);
        k_u2<<<1184, 256>>>(upd_w2 + l * EMB * EMB, upd_b2 + l * EMB,
                            upd_g1 + l * EMB, upd_be1 + l * EMB, l);
    }
    k_u3pool<<<(Nn * 8 + 255) / 256, 256>>>(batch, upd_g2 + (NL - 1) * EMB,
                                            upd_be2 + (NL - 1) * EMB, NL - 1);
    k_pred<<<1, NB * NOUT>>>(pred_w, pred_b, out);
}